// round 6
// baseline (speedup 1.0000x reference)
#include <cuda_runtime.h>
#include <math.h>

#define B   8
#define C   64
#define NP  65536
#define RR  32
#define R3  32768   // 32^3

// Scratch (device globals — zero-initialized at load; every launch restores
// the zero state itself, so no memsets are needed in the graph).
__device__ float g_scratch[(size_t)B * R3 * C];   // [B][R3][C]  channel-contiguous
__device__ float g_cnt[B * R3];                   // per-voxel point counts
__device__ int   g_flat[B * NP];                  // per-point flat voxel id
__device__ float g_stats[B * 4];                  // meanx, meany, meanz, maxsq
__device__ float g_part[B * 32 * 3];              // partial sums for mean

// ---------------------------------------------------------------------------
// K1a: partial sums for mean. 32 chunks per batch, deterministic tree.
// ---------------------------------------------------------------------------
__global__ void sum_part_kernel(const float* __restrict__ coords) {
    const int b     = blockIdx.x >> 5;
    const int chunk = blockIdx.x & 31;
    const int t     = threadIdx.x;            // 256
    const int base  = chunk * 2048;
    const float* cb = coords + (size_t)b * 3 * NP;

    float sx = 0.f, sy = 0.f, sz = 0.f;
#pragma unroll
    for (int k = 0; k < 8; k++) {
        int i = base + t + k * 256;
        sx += cb[i];
        sy += cb[NP + i];
        sz += cb[2 * NP + i];
    }
#pragma unroll
    for (int s = 16; s > 0; s >>= 1) {
        sx += __shfl_down_sync(0xFFFFFFFFu, sx, s);
        sy += __shfl_down_sync(0xFFFFFFFFu, sy, s);
        sz += __shfl_down_sync(0xFFFFFFFFu, sz, s);
    }
    __shared__ float wx[8], wy[8], wz[8];
    if ((t & 31) == 0) { wx[t >> 5] = sx; wy[t >> 5] = sy; wz[t >> 5] = sz; }
    __syncthreads();
    if (t == 0) {
        float ax = 0.f, ay = 0.f, az = 0.f;
#pragma unroll
        for (int w = 0; w < 8; w++) { ax += wx[w]; ay += wy[w]; az += wz[w]; }
        float* p = g_part + ((size_t)b * 32 + chunk) * 3;
        p[0] = ax; p[1] = ay; p[2] = az;
    }
}

// K1b: combine 32 partials -> mean. grid 8, block 96 (3 warps, one per comp).
__global__ void sum_combine_kernel() {
    const int b = blockIdx.x;
    const int t = threadIdx.x;                // 96
    const int comp = t >> 5;
    const int j    = t & 31;
    float v = g_part[((size_t)b * 32 + j) * 3 + comp];
#pragma unroll
    for (int s = 16; s > 0; s >>= 1)
        v += __shfl_down_sync(0xFFFFFFFFu, v, s);
    if (j == 0) g_stats[b * 4 + comp] = v / (float)NP;
}

// K1c: max squared norm of centered coords. atomicMax on float bits (>=0) is
// order-independent -> deterministic. g_stats[b*4+3] is re-zeroed by finalize.
__global__ void maxsq_kernel(const float* __restrict__ coords) {
    const int b     = blockIdx.x >> 5;
    const int chunk = blockIdx.x & 31;
    const int t     = threadIdx.x;            // 256
    const int base  = chunk * 2048;
    const float* cb = coords + (size_t)b * 3 * NP;
    const float mx = g_stats[b * 4 + 0];
    const float my = g_stats[b * 4 + 1];
    const float mz = g_stats[b * 4 + 2];

    float m = 0.f;
#pragma unroll
    for (int k = 0; k < 8; k++) {
        int i = base + t + k * 256;
        float x = cb[i]          - mx;
        float y = cb[NP + i]     - my;
        float z = cb[2 * NP + i] - mz;
        m = fmaxf(m, x * x + y * y + z * z);
    }
#pragma unroll
    for (int s = 16; s > 0; s >>= 1)
        m = fmaxf(m, __shfl_down_sync(0xFFFFFFFFu, m, s));
    __shared__ float wm[8];
    if ((t & 31) == 0) wm[t >> 5] = m;
    __syncthreads();
    if (t == 0) {
#pragma unroll
        for (int w = 1; w < 8; w++) m = fmaxf(m, wm[w]);
        atomicMax((unsigned*)&g_stats[b * 4 + 3], __float_as_uint(m));
    }
}

// ---------------------------------------------------------------------------
// K2: per-point — nc (output), flat voxel id, voxel counts.
// 4 points per thread via float4; reciprocal-scale instead of division.
// ---------------------------------------------------------------------------
__global__ __launch_bounds__(256) void points_kernel(const float* __restrict__ coords,
                                                     float* __restrict__ nc_out) {
    const int q = blockIdx.x * blockDim.x + threadIdx.x;   // float4 index
    const int b  = q >> 14;                                // NP/4 = 16384 quads/batch
    const int n4 = (q & 16383);                            // quad within batch

    const float mx = g_stats[b * 4 + 0];
    const float my = g_stats[b * 4 + 1];
    const float mz = g_stats[b * 4 + 2];
    const float denom = 2.0f * sqrtf(g_stats[b * 4 + 3]);  // EPS = 0
    const float s = (float)RR / denom;                     // (c-m)/denom*RR

    const float4* cb = (const float4*)(coords + (size_t)b * 3 * NP);
    float4 x = cb[n4];
    float4 y = cb[NP / 4 + n4];
    float4 z = cb[2 * (NP / 4) + n4];

    x.x = fminf(fmaxf(fmaf(x.x - mx, s, 16.0f), 0.0f), 31.0f);
    x.y = fminf(fmaxf(fmaf(x.y - mx, s, 16.0f), 0.0f), 31.0f);
    x.z = fminf(fmaxf(fmaf(x.z - mx, s, 16.0f), 0.0f), 31.0f);
    x.w = fminf(fmaxf(fmaf(x.w - mx, s, 16.0f), 0.0f), 31.0f);
    y.x = fminf(fmaxf(fmaf(y.x - my, s, 16.0f), 0.0f), 31.0f);
    y.y = fminf(fmaxf(fmaf(y.y - my, s, 16.0f), 0.0f), 31.0f);
    y.z = fminf(fmaxf(fmaf(y.z - my, s, 16.0f), 0.0f), 31.0f);
    y.w = fminf(fmaxf(fmaf(y.w - my, s, 16.0f), 0.0f), 31.0f);
    z.x = fminf(fmaxf(fmaf(z.x - mz, s, 16.0f), 0.0f), 31.0f);
    z.y = fminf(fmaxf(fmaf(z.y - mz, s, 16.0f), 0.0f), 31.0f);
    z.z = fminf(fmaxf(fmaf(z.z - mz, s, 16.0f), 0.0f), 31.0f);
    z.w = fminf(fmaxf(fmaf(z.w - mz, s, 16.0f), 0.0f), 31.0f);

    float4* nb = (float4*)(nc_out + (size_t)b * 3 * NP);
    nb[n4]               = x;
    nb[NP / 4 + n4]      = y;
    nb[2 * (NP / 4) + n4] = z;

    // jnp.round == round-half-to-even == rintf
    int4 fl;
    fl.x = ((int)rintf(x.x) * RR + (int)rintf(y.x)) * RR + (int)rintf(z.x);
    fl.y = ((int)rintf(x.y) * RR + (int)rintf(y.y)) * RR + (int)rintf(z.y);
    fl.z = ((int)rintf(x.z) * RR + (int)rintf(y.z)) * RR + (int)rintf(z.z);
    fl.w = ((int)rintf(x.w) * RR + (int)rintf(y.w)) * RR + (int)rintf(z.w);
    *(int4*)&g_flat[b * NP + n4 * 4] = fl;

    float* cnt = g_cnt + b * R3;
    atomicAdd(&cnt[fl.x], 1.0f);
    atomicAdd(&cnt[fl.y], 1.0f);
    atomicAdd(&cnt[fl.z], 1.0f);
    atomicAdd(&cnt[fl.w], 1.0f);
}

// ---------------------------------------------------------------------------
// K3: feature scatter, line-coalesced atomics.
// Phase 1: coalesced streaming loads (lane = point, __ldcs so the 128MB
//          feature stream doesn't evict the L2-resident scratch), staged in a
//          128-pt x 64-ch smem tile (row stride 68 floats).
// Phase 2: lanes 0-15 cover all 64 channels (256B) of point A, lanes 16-31 of
//          point B -> one red.v4 instruction touches 4 cache lines.
// ---------------------------------------------------------------------------
#define TPTS 128           // points per block
#define TSTR 68            // smem row stride in floats (272B = 17*16B)

__global__ __launch_bounds__(256) void scatter_kernel(const float* __restrict__ features) {
    const int blk = blockIdx.x;               // B * NP / TPTS = 4096
    const int b   = blk >> 9;                 // 512 blocks per batch
    const int n0  = (blk & 511) * TPTS;
    const int t   = threadIdx.x;              // 256

    __shared__ __align__(16) float tile[TPTS * TSTR];
    __shared__ int sflat[TPTS];

    // ---- Phase 1: load + transpose into smem ----
    {
        const int p  = t & (TPTS - 1);        // point within tile
        const int ch = (t >> 7) * 8;          // channel-quad base: 0 or 8
        const float* f = features + (size_t)b * C * NP + n0 + p;
#pragma unroll
        for (int q = 0; q < 8; q++) {
            const int c = (ch + q) * 4;
            float4 v;
            v.x = __ldcs(f + (size_t)(c + 0) * NP);
            v.y = __ldcs(f + (size_t)(c + 1) * NP);
            v.z = __ldcs(f + (size_t)(c + 2) * NP);
            v.w = __ldcs(f + (size_t)(c + 3) * NP);
            *(float4*)&tile[p * TSTR + c] = v;
        }
        if (t < TPTS) sflat[t] = g_flat[b * NP + n0 + t];
    }
    __syncthreads();

    // ---- Phase 2: coalesced-lane reds ----
    {
        const int w    = t >> 5;              // warp 0..7, 16 points each
        const int l    = t & 31;
        const int half = l >> 4;              // 0 -> point A, 1 -> point B
        const int lc   = (l & 15) * 4;        // channel offset
        float* sbase = g_scratch + (size_t)b * R3 * C;
#pragma unroll
        for (int i = 0; i < 8; i++) {
            const int p = w * 16 + 2 * i + half;
            const int flat = sflat[p];
            const float4 v = *(const float4*)&tile[p * TSTR + lc];
            float* dst = sbase + (size_t)flat * C + lc;
            asm volatile("red.global.add.v4.f32 [%0], {%1, %2, %3, %4};"
                         :: "l"(dst), "f"(v.x), "f"(v.y), "f"(v.z), "f"(v.w)
                         : "memory");
        }
    }
}

// ---------------------------------------------------------------------------
// K4: normalize by count + transpose [B][R3][C] -> [B][C][R3], and restore
// all scratch state to zero for the next graph replay (replaces 3 memsets).
// ---------------------------------------------------------------------------
__global__ __launch_bounds__(256) void finalize_kernel(float* __restrict__ out) {
    const int blk = blockIdx.x;               // B * R3 / 64 = 4096
    const int b   = blk >> 9;                 // 512 blocks per batch
    const int v0  = (blk & 511) * 64;
    const int t   = threadIdx.x;              // 256

    __shared__ float tile[64 * 65];
    __shared__ float inv[64];

    float4* src = (float4*)(g_scratch + ((size_t)b * R3 + v0) * C);
    const float4 zero4 = make_float4(0.f, 0.f, 0.f, 0.f);
#pragma unroll
    for (int it = 0; it < 4; it++) {
        const int i = t + it * 256;           // float4 index (1024 total)
        const float4 u = src[i];
        src[i] = zero4;                       // re-zero scratch (L2-hot)
        const int g = i * 4;
        const int v = g >> 6, c = g & 63;
        tile[v * 65 + c + 0] = u.x;
        tile[v * 65 + c + 1] = u.y;
        tile[v * 65 + c + 2] = u.z;
        tile[v * 65 + c + 3] = u.w;
    }
    if (t < 64) {
        inv[t] = 1.0f / fmaxf(g_cnt[b * R3 + v0 + t], 1.0f);
        g_cnt[b * R3 + v0 + t] = 0.0f;        // re-zero counts
    }
    if ((blk & 511) == 0 && t == 64) {
        g_stats[b * 4 + 3] = 0.0f;            // re-zero maxsq accumulator
    }
    __syncthreads();

    float* dst = out + (size_t)b * C * R3 + v0;
#pragma unroll
    for (int it = 0; it < 4; it++) {
        const int i = t + it * 256;
        const int g = i * 4;
        const int c = g >> 6, v = g & 63;
        float4 r;
        r.x = tile[(v + 0) * 65 + c] * inv[v + 0];
        r.y = tile[(v + 1) * 65 + c] * inv[v + 1];
        r.z = tile[(v + 2) * 65 + c] * inv[v + 2];
        r.w = tile[(v + 3) * 65 + c] * inv[v + 3];
        *(float4*)&dst[(size_t)c * R3 + v] = r;
    }
}

// ---------------------------------------------------------------------------
extern "C" void kernel_launch(void* const* d_in, const int* in_sizes, int n_in,
                              void* d_out, int out_size) {
    const float* features = (const float*)d_in[0];
    const float* coords   = (const float*)d_in[1];
    if (n_in >= 2 && in_sizes[0] < in_sizes[1]) {
        features = (const float*)d_in[1];
        coords   = (const float*)d_in[0];
    }

    float* out    = (float*)d_out;
    float* nc_out = out + (size_t)B * C * R3;   // nc follows vox_feat in d_out

    sum_part_kernel<<<B * 32, 256>>>(coords);
    sum_combine_kernel<<<B, 96>>>();
    maxsq_kernel<<<B * 32, 256>>>(coords);
    points_kernel<<<(B * NP / 4) / 256, 256>>>(coords, nc_out);
    scatter_kernel<<<(B * NP) / TPTS, 256>>>(features);
    finalize_kernel<<<(B * R3) / 64, 256>>>(out);
}

// round 7
// speedup vs baseline: 1.5037x; 1.5037x over previous
#include <cuda_runtime.h>
#include <math.h>

#define B   8
#define C   64
#define NP  65536
#define RR  32
#define R3  32768   // 32^3

// Scratch (device globals — no allocation allowed in kernel_launch)
__device__ float g_scratch[(size_t)B * R3 * C];   // [B][R3][C]  channel-contiguous
__device__ float g_cnt[B * R3];                   // per-voxel point counts
__device__ int   g_flat[B * NP];                  // per-point flat voxel id
__device__ float g_stats[B * 4];                  // meanx, meany, meanz, maxsq
__device__ float g_part[B * 32 * 3];              // partial sums for mean

// ---------------------------------------------------------------------------
// K1a: partial sums for mean. 32 chunks per batch, deterministic tree.
// ---------------------------------------------------------------------------
__global__ void sum_part_kernel(const float* __restrict__ coords) {
    const int b     = blockIdx.x >> 5;
    const int chunk = blockIdx.x & 31;
    const int t     = threadIdx.x;            // 256
    const int base  = chunk * 2048;
    const float* cb = coords + (size_t)b * 3 * NP;

    float sx = 0.f, sy = 0.f, sz = 0.f;
#pragma unroll
    for (int k = 0; k < 8; k++) {
        int i = base + t + k * 256;
        sx += cb[i];
        sy += cb[NP + i];
        sz += cb[2 * NP + i];
    }
#pragma unroll
    for (int s = 16; s > 0; s >>= 1) {
        sx += __shfl_down_sync(0xFFFFFFFFu, sx, s);
        sy += __shfl_down_sync(0xFFFFFFFFu, sy, s);
        sz += __shfl_down_sync(0xFFFFFFFFu, sz, s);
    }
    __shared__ float wx[8], wy[8], wz[8];
    if ((t & 31) == 0) { wx[t >> 5] = sx; wy[t >> 5] = sy; wz[t >> 5] = sz; }
    __syncthreads();
    if (t == 0) {
        float ax = 0.f, ay = 0.f, az = 0.f;
#pragma unroll
        for (int w = 0; w < 8; w++) { ax += wx[w]; ay += wy[w]; az += wz[w]; }
        float* p = g_part + ((size_t)b * 32 + chunk) * 3;
        p[0] = ax; p[1] = ay; p[2] = az;
    }
}

// K1b: combine 32 partials -> mean. grid 8, block 96 (3 warps, one per comp).
__global__ void sum_combine_kernel() {
    const int b = blockIdx.x;
    const int t = threadIdx.x;                // 96
    const int comp = t >> 5;
    const int j    = t & 31;
    float v = g_part[((size_t)b * 32 + j) * 3 + comp];
#pragma unroll
    for (int s = 16; s > 0; s >>= 1)
        v += __shfl_down_sync(0xFFFFFFFFu, v, s);
    if (j == 0) g_stats[b * 4 + comp] = v / (float)NP;
}

// K1c: max squared norm of centered coords. atomicMax on float bits (>=0) is
// order-independent -> deterministic. Slot is zeroed by the memset each launch.
__global__ void maxsq_kernel(const float* __restrict__ coords) {
    const int b     = blockIdx.x >> 5;
    const int chunk = blockIdx.x & 31;
    const int t     = threadIdx.x;            // 256
    const int base  = chunk * 2048;
    const float* cb = coords + (size_t)b * 3 * NP;
    const float mx = g_stats[b * 4 + 0];
    const float my = g_stats[b * 4 + 1];
    const float mz = g_stats[b * 4 + 2];

    float m = 0.f;
#pragma unroll
    for (int k = 0; k < 8; k++) {
        int i = base + t + k * 256;
        float x = cb[i]          - mx;
        float y = cb[NP + i]     - my;
        float z = cb[2 * NP + i] - mz;
        m = fmaxf(m, x * x + y * y + z * z);
    }
#pragma unroll
    for (int s = 16; s > 0; s >>= 1)
        m = fmaxf(m, __shfl_down_sync(0xFFFFFFFFu, m, s));
    __shared__ float wm[8];
    if ((t & 31) == 0) wm[t >> 5] = m;
    __syncthreads();
    if (t == 0) {
#pragma unroll
        for (int w = 1; w < 8; w++) m = fmaxf(m, wm[w]);
        atomicMax((unsigned*)&g_stats[b * 4 + 3], __float_as_uint(m));
    }
}

// ---------------------------------------------------------------------------
// K2: per-point — nc (output), flat voxel id, voxel counts.
// 4 points per thread via float4; reciprocal-scale instead of division.
// ---------------------------------------------------------------------------
__global__ __launch_bounds__(256) void points_kernel(const float* __restrict__ coords,
                                                     float* __restrict__ nc_out) {
    const int q = blockIdx.x * blockDim.x + threadIdx.x;   // float4 index
    const int b  = q >> 14;                                // NP/4 = 16384 quads/batch
    const int n4 = (q & 16383);                            // quad within batch

    const float mx = g_stats[b * 4 + 0];
    const float my = g_stats[b * 4 + 1];
    const float mz = g_stats[b * 4 + 2];
    const float denom = 2.0f * sqrtf(g_stats[b * 4 + 3]);  // EPS = 0
    const float s = (float)RR / denom;                     // (c-m)/denom*RR

    const float4* cb = (const float4*)(coords + (size_t)b * 3 * NP);
    float4 x = cb[n4];
    float4 y = cb[NP / 4 + n4];
    float4 z = cb[2 * (NP / 4) + n4];

    x.x = fminf(fmaxf(fmaf(x.x - mx, s, 16.0f), 0.0f), 31.0f);
    x.y = fminf(fmaxf(fmaf(x.y - mx, s, 16.0f), 0.0f), 31.0f);
    x.z = fminf(fmaxf(fmaf(x.z - mx, s, 16.0f), 0.0f), 31.0f);
    x.w = fminf(fmaxf(fmaf(x.w - mx, s, 16.0f), 0.0f), 31.0f);
    y.x = fminf(fmaxf(fmaf(y.x - my, s, 16.0f), 0.0f), 31.0f);
    y.y = fminf(fmaxf(fmaf(y.y - my, s, 16.0f), 0.0f), 31.0f);
    y.z = fminf(fmaxf(fmaf(y.z - my, s, 16.0f), 0.0f), 31.0f);
    y.w = fminf(fmaxf(fmaf(y.w - my, s, 16.0f), 0.0f), 31.0f);
    z.x = fminf(fmaxf(fmaf(z.x - mz, s, 16.0f), 0.0f), 31.0f);
    z.y = fminf(fmaxf(fmaf(z.y - mz, s, 16.0f), 0.0f), 31.0f);
    z.z = fminf(fmaxf(fmaf(z.z - mz, s, 16.0f), 0.0f), 31.0f);
    z.w = fminf(fmaxf(fmaf(z.w - mz, s, 16.0f), 0.0f), 31.0f);

    float4* nb = (float4*)(nc_out + (size_t)b * 3 * NP);
    nb[n4]                = x;
    nb[NP / 4 + n4]       = y;
    nb[2 * (NP / 4) + n4] = z;

    // jnp.round == round-half-to-even == rintf
    int4 fl;
    fl.x = ((int)rintf(x.x) * RR + (int)rintf(y.x)) * RR + (int)rintf(z.x);
    fl.y = ((int)rintf(x.y) * RR + (int)rintf(y.y)) * RR + (int)rintf(z.y);
    fl.z = ((int)rintf(x.z) * RR + (int)rintf(y.z)) * RR + (int)rintf(z.z);
    fl.w = ((int)rintf(x.w) * RR + (int)rintf(y.w)) * RR + (int)rintf(z.w);
    *(int4*)&g_flat[b * NP + n4 * 4] = fl;

    float* cnt = g_cnt + b * R3;
    atomicAdd(&cnt[fl.x], 1.0f);
    atomicAdd(&cnt[fl.y], 1.0f);
    atomicAdd(&cnt[fl.z], 1.0f);
    atomicAdd(&cnt[fl.w], 1.0f);
}

// ---------------------------------------------------------------------------
// K3: feature scatter, line-coalesced atomics.
// Phase 1: coalesced STREAMING loads (lane = point, __ldcs: evict-first, so
//          the 128MB feature stream doesn't evict the freshly-memset,
//          L2-resident scratch), staged in a 128-pt x 64-ch smem tile
//          (row stride 68 floats -> conflict-free 16B groups).
// Phase 2: lanes 0-15 cover all 64 channels (256B contiguous) of point A,
//          lanes 16-31 of point B -> one red.v4 touches only 4 cache lines.
// ---------------------------------------------------------------------------
#define TPTS 128           // points per block
#define TSTR 68            // smem row stride in floats (272B = 17*16B)

__global__ __launch_bounds__(256) void scatter_kernel(const float* __restrict__ features) {
    const int blk = blockIdx.x;               // B * NP / TPTS = 4096
    const int b   = blk >> 9;                 // 512 blocks per batch
    const int n0  = (blk & 511) * TPTS;
    const int t   = threadIdx.x;              // 256

    __shared__ __align__(16) float tile[TPTS * TSTR];
    __shared__ int sflat[TPTS];

    // ---- Phase 1: load + transpose into smem ----
    {
        const int p  = t & (TPTS - 1);        // point within tile
        const int ch = (t >> 7) * 8;          // channel-quad base: 0 or 8
        const float* f = features + (size_t)b * C * NP + n0 + p;
#pragma unroll
        for (int q = 0; q < 8; q++) {
            const int c = (ch + q) * 4;
            float4 v;
            v.x = __ldcs(f + (size_t)(c + 0) * NP);
            v.y = __ldcs(f + (size_t)(c + 1) * NP);
            v.z = __ldcs(f + (size_t)(c + 2) * NP);
            v.w = __ldcs(f + (size_t)(c + 3) * NP);
            *(float4*)&tile[p * TSTR + c] = v;
        }
        if (t < TPTS) sflat[t] = g_flat[b * NP + n0 + t];
    }
    __syncthreads();

    // ---- Phase 2: coalesced-lane reds ----
    {
        const int w    = t >> 5;              // warp 0..7, 16 points each
        const int l    = t & 31;
        const int half = l >> 4;              // 0 -> point A, 1 -> point B
        const int lc   = (l & 15) * 4;        // channel offset
        float* sbase = g_scratch + (size_t)b * R3 * C;
#pragma unroll
        for (int i = 0; i < 8; i++) {
            const int p = w * 16 + 2 * i + half;
            const int flat = sflat[p];
            const float4 v = *(const float4*)&tile[p * TSTR + lc];
            float* dst = sbase + (size_t)flat * C + lc;
            asm volatile("red.global.add.v4.f32 [%0], {%1, %2, %3, %4};"
                         :: "l"(dst), "f"(v.x), "f"(v.y), "f"(v.z), "f"(v.w)
                         : "memory");
        }
    }
}

// ---------------------------------------------------------------------------
// K4: normalize by count + transpose [B][R3][C] -> [B][C][R3].
// 64-voxel tile, float4 loads, streaming float4 stores (output never re-read).
// ---------------------------------------------------------------------------
__global__ __launch_bounds__(256) void finalize_kernel(float* __restrict__ out) {
    const int blk = blockIdx.x;               // B * R3 / 64 = 4096
    const int b   = blk >> 9;                 // 512 blocks per batch
    const int v0  = (blk & 511) * 64;
    const int t   = threadIdx.x;              // 256

    __shared__ float tile[64 * 65];
    __shared__ float inv[64];

    const float4* src = (const float4*)(g_scratch + ((size_t)b * R3 + v0) * C);
#pragma unroll
    for (int it = 0; it < 4; it++) {
        const int i = t + it * 256;           // float4 index (1024 total)
        const float4 u = src[i];
        const int g = i * 4;
        const int v = g >> 6, c = g & 63;
        tile[v * 65 + c + 0] = u.x;
        tile[v * 65 + c + 1] = u.y;
        tile[v * 65 + c + 2] = u.z;
        tile[v * 65 + c + 3] = u.w;
    }
    if (t < 64) inv[t] = 1.0f / fmaxf(g_cnt[b * R3 + v0 + t], 1.0f);
    __syncthreads();

    float* dst = out + (size_t)b * C * R3 + v0;
#pragma unroll
    for (int it = 0; it < 4; it++) {
        const int i = t + it * 256;
        const int g = i * 4;
        const int c = g >> 5 >> 1, v = g & 63;   // c = g/64
        float4 r;
        r.x = tile[(v + 0) * 65 + c] * inv[v + 0];
        r.y = tile[(v + 1) * 65 + c] * inv[v + 1];
        r.z = tile[(v + 2) * 65 + c] * inv[v + 2];
        r.w = tile[(v + 3) * 65 + c] * inv[v + 3];
        __stcs((float4*)&dst[(size_t)c * R3 + v], r);
    }
}

// ---------------------------------------------------------------------------
extern "C" void kernel_launch(void* const* d_in, const int* in_sizes, int n_in,
                              void* d_out, int out_size) {
    const float* features = (const float*)d_in[0];
    const float* coords   = (const float*)d_in[1];
    if (n_in >= 2 && in_sizes[0] < in_sizes[1]) {
        features = (const float*)d_in[1];
        coords   = (const float*)d_in[0];
    }

    float* out    = (float*)d_out;
    float* nc_out = out + (size_t)B * C * R3;   // nc follows vox_feat in d_out

    void *pScratch = nullptr, *pCnt = nullptr, *pStats = nullptr;
    cudaGetSymbolAddress(&pScratch, g_scratch);
    cudaGetSymbolAddress(&pCnt, g_cnt);
    cudaGetSymbolAddress(&pStats, g_stats);
    cudaMemsetAsync(pScratch, 0, sizeof(float) * (size_t)B * R3 * C);
    cudaMemsetAsync(pCnt,     0, sizeof(float) * (size_t)B * R3);
    cudaMemsetAsync(pStats,   0, sizeof(float) * (size_t)B * 4);

    sum_part_kernel<<<B * 32, 256>>>(coords);
    sum_combine_kernel<<<B, 96>>>();
    maxsq_kernel<<<B * 32, 256>>>(coords);
    points_kernel<<<(B * NP / 4) / 256, 256>>>(coords, nc_out);
    scatter_kernel<<<(B * NP) / TPTS, 256>>>(features);
    finalize_kernel<<<(B * R3) / 64, 256>>>(out);
}

// round 8
// speedup vs baseline: 1.5613x; 1.0383x over previous
#include <cuda_runtime.h>
#include <math.h>

#define B   8
#define C   64
#define NP  65536
#define RR  32
#define R3  32768   // 32^3

#define NBLK 256           // fused-kernel grid (32 blocks per batch)

// Scratch (device globals — no allocation allowed in kernel_launch)
__device__ float g_scratch[(size_t)B * R3 * C];   // [B][R3][C]  channel-contiguous
__device__ float g_cnt[B * R3];                   // per-voxel point counts
__device__ int   g_flat[B * NP];                  // per-point flat voxel id
__device__ float g_maxsq[B];                      // atomicMax accumulator (float bits)
__device__ float g_part[B * 32 * 3];              // partial sums for mean

// Grid-wide software barrier state (replay-safe: gen is monotone, count
// resets to 0 after each use; each barrier slot is used exactly once/launch).
__device__ unsigned g_barcnt[2];
__device__ unsigned g_bargen[2];

__device__ __forceinline__ unsigned ld_acq(const unsigned* p) {
    unsigned v;
    asm volatile("ld.acquire.gpu.u32 %0, [%1];" : "=r"(v) : "l"(p));
    return v;
}

__device__ __forceinline__ void grid_barrier(int slot) {
    __syncthreads();
    if (threadIdx.x == 0) {
        __threadfence();
        const unsigned gen = ld_acq(&g_bargen[slot]);      // snapshot BEFORE arrive
        const unsigned old = atomicAdd(&g_barcnt[slot], 1u);
        if (old == NBLK - 1) {
            atomicExch(&g_barcnt[slot], 0u);               // reset for next launch
            atomicAdd(&g_bargen[slot], 1u);                // release
        } else {
            while (ld_acq(&g_bargen[slot]) == gen) __nanosleep(64);
        }
        __threadfence();
    }
    __syncthreads();
}

// ---------------------------------------------------------------------------
// Fused stats + points kernel. Grid = 256 blocks x 256 threads.
// Block (b, chunk) owns points [chunk*2048, (chunk+1)*2048) of batch b.
//   Phase A: partial coord sums -> g_part            | zero maxsq slot
//   ── grid barrier 0 ──
//   Phase B: every block re-reduces its batch's 32 partials -> mean (bitwise
//            identical across blocks; coords now L2-hot)
//   Phase C: local max ||c-mean||^2 -> atomicMax(g_maxsq[b]) (order-indep)
//   ── grid barrier 1 ──
//   Phase D: nc output, flat voxel ids, count atomics
// ---------------------------------------------------------------------------
__global__ __launch_bounds__(256) void fused_stats_points_kernel(
        const float* __restrict__ coords, float* __restrict__ nc_out) {
    const int b     = blockIdx.x >> 5;
    const int chunk = blockIdx.x & 31;
    const int t     = threadIdx.x;            // 256
    const int base  = chunk * 2048;
    const float* cb = coords + (size_t)b * 3 * NP;

    __shared__ float wx[8], wy[8], wz[8];
    __shared__ float s_mean[3];
    __shared__ float s_denom;

    // ---- Phase A: partial sums ----
    {
        float sx = 0.f, sy = 0.f, sz = 0.f;
#pragma unroll
        for (int k = 0; k < 8; k++) {
            int i = base + t + k * 256;
            sx += cb[i];
            sy += cb[NP + i];
            sz += cb[2 * NP + i];
        }
#pragma unroll
        for (int s = 16; s > 0; s >>= 1) {
            sx += __shfl_down_sync(0xFFFFFFFFu, sx, s);
            sy += __shfl_down_sync(0xFFFFFFFFu, sy, s);
            sz += __shfl_down_sync(0xFFFFFFFFu, sz, s);
        }
        if ((t & 31) == 0) { wx[t >> 5] = sx; wy[t >> 5] = sy; wz[t >> 5] = sz; }
        __syncthreads();
        if (t == 0) {
            float ax = 0.f, ay = 0.f, az = 0.f;
#pragma unroll
            for (int w = 0; w < 8; w++) { ax += wx[w]; ay += wy[w]; az += wz[w]; }
            float* p = g_part + ((size_t)b * 32 + chunk) * 3;
            p[0] = ax; p[1] = ay; p[2] = az;
            if (chunk == 0) g_maxsq[b] = 0.0f;   // zero accumulator (pre-barrier)
        }
    }
    grid_barrier(0);

    // ---- Phase B: mean from the 32 partials (warp 0, identical all blocks) ----
    if (t < 32) {
        const float* p = g_part + ((size_t)b * 32 + t) * 3;
        float px = p[0], py = p[1], pz = p[2];
#pragma unroll
        for (int s = 16; s > 0; s >>= 1) {
            px += __shfl_down_sync(0xFFFFFFFFu, px, s);
            py += __shfl_down_sync(0xFFFFFFFFu, py, s);
            pz += __shfl_down_sync(0xFFFFFFFFu, pz, s);
        }
        if (t == 0) {
            s_mean[0] = px / (float)NP;
            s_mean[1] = py / (float)NP;
            s_mean[2] = pz / (float)NP;
        }
    }
    __syncthreads();
    const float mx = s_mean[0], my = s_mean[1], mz = s_mean[2];

    // ---- Phase C: max squared norm ----
    {
        float m = 0.f;
#pragma unroll
        for (int k = 0; k < 8; k++) {
            int i = base + t + k * 256;
            float x = cb[i]          - mx;
            float y = cb[NP + i]     - my;
            float z = cb[2 * NP + i] - mz;
            m = fmaxf(m, x * x + y * y + z * z);
        }
#pragma unroll
        for (int s = 16; s > 0; s >>= 1)
            m = fmaxf(m, __shfl_down_sync(0xFFFFFFFFu, m, s));
        if ((t & 31) == 0) wx[t >> 5] = m;
        __syncthreads();
        if (t == 0) {
#pragma unroll
            for (int w = 1; w < 8; w++) m = fmaxf(m, wx[w]);
            atomicMax((unsigned*)&g_maxsq[b], __float_as_uint(m));
        }
    }
    grid_barrier(1);

    // ---- Phase D: nc + flat ids + counts (8 points = 2 float4-quads/thread) ----
    if (t == 0) s_denom = 2.0f * sqrtf(g_maxsq[b]);   // EPS = 0
    __syncthreads();
    const float sc = (float)RR / s_denom;

    const float4* c4 = (const float4*)cb;
    float4* nb = (float4*)(nc_out + (size_t)b * 3 * NP);
    float* cnt = g_cnt + b * R3;
    const int q0 = chunk * 512;               // quad base for this block

#pragma unroll
    for (int k = 0; k < 2; k++) {
        const int n4 = q0 + t + k * 256;
        float4 x = c4[n4];
        float4 y = c4[NP / 4 + n4];
        float4 z = c4[2 * (NP / 4) + n4];

        x.x = fminf(fmaxf(fmaf(x.x - mx, sc, 16.0f), 0.0f), 31.0f);
        x.y = fminf(fmaxf(fmaf(x.y - mx, sc, 16.0f), 0.0f), 31.0f);
        x.z = fminf(fmaxf(fmaf(x.z - mx, sc, 16.0f), 0.0f), 31.0f);
        x.w = fminf(fmaxf(fmaf(x.w - mx, sc, 16.0f), 0.0f), 31.0f);
        y.x = fminf(fmaxf(fmaf(y.x - my, sc, 16.0f), 0.0f), 31.0f);
        y.y = fminf(fmaxf(fmaf(y.y - my, sc, 16.0f), 0.0f), 31.0f);
        y.z = fminf(fmaxf(fmaf(y.z - my, sc, 16.0f), 0.0f), 31.0f);
        y.w = fminf(fmaxf(fmaf(y.w - my, sc, 16.0f), 0.0f), 31.0f);
        z.x = fminf(fmaxf(fmaf(z.x - mz, sc, 16.0f), 0.0f), 31.0f);
        z.y = fminf(fmaxf(fmaf(z.y - mz, sc, 16.0f), 0.0f), 31.0f);
        z.z = fminf(fmaxf(fmaf(z.z - mz, sc, 16.0f), 0.0f), 31.0f);
        z.w = fminf(fmaxf(fmaf(z.w - mz, sc, 16.0f), 0.0f), 31.0f);

        __stcs(&nb[n4],                x);
        __stcs(&nb[NP / 4 + n4],       y);
        __stcs(&nb[2 * (NP / 4) + n4], z);

        // jnp.round == round-half-to-even == rintf
        int4 fl;
        fl.x = ((int)rintf(x.x) * RR + (int)rintf(y.x)) * RR + (int)rintf(z.x);
        fl.y = ((int)rintf(x.y) * RR + (int)rintf(y.y)) * RR + (int)rintf(z.y);
        fl.z = ((int)rintf(x.z) * RR + (int)rintf(y.z)) * RR + (int)rintf(z.z);
        fl.w = ((int)rintf(x.w) * RR + (int)rintf(y.w)) * RR + (int)rintf(z.w);
        *(int4*)&g_flat[b * NP + n4 * 4] = fl;

        atomicAdd(&cnt[fl.x], 1.0f);
        atomicAdd(&cnt[fl.y], 1.0f);
        atomicAdd(&cnt[fl.z], 1.0f);
        atomicAdd(&cnt[fl.w], 1.0f);
    }
}

// ---------------------------------------------------------------------------
// K3: feature scatter, line-coalesced atomics.
// Phase 1: coalesced STREAMING loads (lane = point, __ldcs: evict-first, so
//          the 128MB feature stream doesn't evict the freshly-memset,
//          L2-resident scratch), staged in a 128-pt x 64-ch smem tile
//          (row stride 68 floats -> conflict-free 16B groups).
// Phase 2: lanes 0-15 cover all 64 channels (256B contiguous) of point A,
//          lanes 16-31 of point B -> one red.v4 touches only 4 cache lines.
// ---------------------------------------------------------------------------
#define TPTS 128           // points per block
#define TSTR 68            // smem row stride in floats (272B = 17*16B)

__global__ __launch_bounds__(256) void scatter_kernel(const float* __restrict__ features) {
    const int blk = blockIdx.x;               // B * NP / TPTS = 4096
    const int b   = blk >> 9;                 // 512 blocks per batch
    const int n0  = (blk & 511) * TPTS;
    const int t   = threadIdx.x;              // 256

    __shared__ __align__(16) float tile[TPTS * TSTR];
    __shared__ int sflat[TPTS];

    // ---- Phase 1: load + transpose into smem ----
    {
        const int p  = t & (TPTS - 1);        // point within tile
        const int ch = (t >> 7) * 8;          // channel-quad base: 0 or 8
        const float* f = features + (size_t)b * C * NP + n0 + p;
#pragma unroll
        for (int q = 0; q < 8; q++) {
            const int c = (ch + q) * 4;
            float4 v;
            v.x = __ldcs(f + (size_t)(c + 0) * NP);
            v.y = __ldcs(f + (size_t)(c + 1) * NP);
            v.z = __ldcs(f + (size_t)(c + 2) * NP);
            v.w = __ldcs(f + (size_t)(c + 3) * NP);
            *(float4*)&tile[p * TSTR + c] = v;
        }
        if (t < TPTS) sflat[t] = g_flat[b * NP + n0 + t];
    }
    __syncthreads();

    // ---- Phase 2: coalesced-lane reds ----
    {
        const int w    = t >> 5;              // warp 0..7, 16 points each
        const int l    = t & 31;
        const int half = l >> 4;              // 0 -> point A, 1 -> point B
        const int lc   = (l & 15) * 4;        // channel offset
        float* sbase = g_scratch + (size_t)b * R3 * C;
#pragma unroll
        for (int i = 0; i < 8; i++) {
            const int p = w * 16 + 2 * i + half;
            const int flat = sflat[p];
            const float4 v = *(const float4*)&tile[p * TSTR + lc];
            float* dst = sbase + (size_t)flat * C + lc;
            asm volatile("red.global.add.v4.f32 [%0], {%1, %2, %3, %4};"
                         :: "l"(dst), "f"(v.x), "f"(v.y), "f"(v.z), "f"(v.w)
                         : "memory");
        }
    }
}

// ---------------------------------------------------------------------------
// K4: normalize by count + transpose [B][R3][C] -> [B][C][R3].
// 64-voxel tile, float4 loads, streaming float4 stores (output never re-read).
// ---------------------------------------------------------------------------
__global__ __launch_bounds__(256) void finalize_kernel(float* __restrict__ out) {
    const int blk = blockIdx.x;               // B * R3 / 64 = 4096
    const int b   = blk >> 9;                 // 512 blocks per batch
    const int v0  = (blk & 511) * 64;
    const int t   = threadIdx.x;              // 256

    __shared__ float tile[64 * 65];
    __shared__ float inv[64];

    const float4* src = (const float4*)(g_scratch + ((size_t)b * R3 + v0) * C);
#pragma unroll
    for (int it = 0; it < 4; it++) {
        const int i = t + it * 256;           // float4 index (1024 total)
        const float4 u = src[i];
        const int g = i * 4;
        const int v = g >> 6, c = g & 63;
        tile[v * 65 + c + 0] = u.x;
        tile[v * 65 + c + 1] = u.y;
        tile[v * 65 + c + 2] = u.z;
        tile[v * 65 + c + 3] = u.w;
    }
    if (t < 64) inv[t] = 1.0f / fmaxf(g_cnt[b * R3 + v0 + t], 1.0f);
    __syncthreads();

    float* dst = out + (size_t)b * C * R3 + v0;
#pragma unroll
    for (int it = 0; it < 4; it++) {
        const int i = t + it * 256;
        const int g = i * 4;
        const int c = g >> 6, v = g & 63;
        float4 r;
        r.x = tile[(v + 0) * 65 + c] * inv[v + 0];
        r.y = tile[(v + 1) * 65 + c] * inv[v + 1];
        r.z = tile[(v + 2) * 65 + c] * inv[v + 2];
        r.w = tile[(v + 3) * 65 + c] * inv[v + 3];
        __stcs((float4*)&dst[(size_t)c * R3 + v], r);
    }
}

// ---------------------------------------------------------------------------
extern "C" void kernel_launch(void* const* d_in, const int* in_sizes, int n_in,
                              void* d_out, int out_size) {
    const float* features = (const float*)d_in[0];
    const float* coords   = (const float*)d_in[1];
    if (n_in >= 2 && in_sizes[0] < in_sizes[1]) {
        features = (const float*)d_in[1];
        coords   = (const float*)d_in[0];
    }

    float* out    = (float*)d_out;
    float* nc_out = out + (size_t)B * C * R3;   // nc follows vox_feat in d_out

    void *pScratch = nullptr, *pCnt = nullptr;
    cudaGetSymbolAddress(&pScratch, g_scratch);
    cudaGetSymbolAddress(&pCnt, g_cnt);
    cudaMemsetAsync(pScratch, 0, sizeof(float) * (size_t)B * R3 * C);
    cudaMemsetAsync(pCnt,     0, sizeof(float) * (size_t)B * R3);

    fused_stats_points_kernel<<<NBLK, 256>>>(coords, nc_out);
    scatter_kernel<<<(B * NP) / TPTS, 256>>>(features);
    finalize_kernel<<<(B * R3) / 64, 256>>>(out);
}

// round 9
// speedup vs baseline: 1.5843x; 1.0147x over previous
#include <cuda_runtime.h>
#include <math.h>

#define B   8
#define C   64
#define NP  65536
#define RR  32
#define R3  32768   // 32^3

#define NBLK   1024        // fused-kernel grid (128 chunks per batch)
#define CHUNKS 128         // chunks per batch
#define CPTS   512         // points per chunk

// Scratch (device globals — no allocation allowed in kernel_launch)
__device__ float g_scratch[(size_t)B * R3 * C];   // [B][R3][C]  channel-contiguous
__device__ float g_cnt[B * R3];                   // per-voxel point counts
__device__ int   g_flat[B * NP];                  // per-point flat voxel id
__device__ float g_maxsq[B];                      // atomicMax accumulator (float bits)
__device__ float g_part[B * CHUNKS * 3];          // partial sums for mean

// Grid-wide software barrier state (replay-safe: gen is monotone, count
// resets to 0 after each use; each barrier slot is used exactly once/launch).
__device__ unsigned g_barcnt[2];
__device__ unsigned g_bargen[2];

__device__ __forceinline__ unsigned ld_acq(const unsigned* p) {
    unsigned v;
    asm volatile("ld.acquire.gpu.u32 %0, [%1];" : "=r"(v) : "l"(p));
    return v;
}

__device__ __forceinline__ void grid_barrier(int slot) {
    __syncthreads();
    if (threadIdx.x == 0) {
        __threadfence();
        const unsigned gen = ld_acq(&g_bargen[slot]);      // snapshot BEFORE arrive
        const unsigned old = atomicAdd(&g_barcnt[slot], 1u);
        if (old == NBLK - 1) {
            atomicExch(&g_barcnt[slot], 0u);               // reset for next launch
            atomicAdd(&g_bargen[slot], 1u);                // release
        } else {
            while (ld_acq(&g_bargen[slot]) == gen) __nanosleep(64);
        }
        __threadfence();
    }
    __syncthreads();
}

// ---------------------------------------------------------------------------
// Fused stats + points kernel. Grid = 1024 blocks x 256 threads.
// __launch_bounds__(256, 7): regs <= 36 -> 7 blocks/SM guaranteed co-resident
// (7 * 148 = 1036 >= 1024), required for the grid barriers.
// Block (b, chunk) owns points [chunk*512, (chunk+1)*512) of batch b.
//   Phase A: partial coord sums -> g_part            | zero maxsq slot
//   ── grid barrier 0 ──
//   Phase B: every block re-reduces its batch's 128 partials -> mean (bitwise
//            identical across blocks; coords now L2-hot)
//   Phase C: local max ||c-mean||^2 -> atomicMax(g_maxsq[b]) (order-indep)
//   ── grid barrier 1 ──
//   Phase D: nc output, flat voxel ids, count atomics (2 points/thread, float2)
// ---------------------------------------------------------------------------
__global__ __launch_bounds__(256, 7) void fused_stats_points_kernel(
        const float* __restrict__ coords, float* __restrict__ nc_out) {
    const int b     = blockIdx.x >> 7;
    const int chunk = blockIdx.x & (CHUNKS - 1);
    const int t     = threadIdx.x;            // 256
    const int base  = chunk * CPTS;
    const float* cb = coords + (size_t)b * 3 * NP;

    __shared__ float wx[8], wy[8], wz[8];
    __shared__ float s_mean[3];
    __shared__ float s_denom;

    // ---- Phase A: partial sums (512 points: 2 scalars/thread/comp) ----
    {
        const int i1 = base + t, i2 = base + t + 256;
        float sx = cb[i1] + cb[i2];
        float sy = cb[NP + i1] + cb[NP + i2];
        float sz = cb[2 * NP + i1] + cb[2 * NP + i2];
#pragma unroll
        for (int s = 16; s > 0; s >>= 1) {
            sx += __shfl_down_sync(0xFFFFFFFFu, sx, s);
            sy += __shfl_down_sync(0xFFFFFFFFu, sy, s);
            sz += __shfl_down_sync(0xFFFFFFFFu, sz, s);
        }
        if ((t & 31) == 0) { wx[t >> 5] = sx; wy[t >> 5] = sy; wz[t >> 5] = sz; }
        __syncthreads();
        if (t == 0) {
            float ax = 0.f, ay = 0.f, az = 0.f;
#pragma unroll
            for (int w = 0; w < 8; w++) { ax += wx[w]; ay += wy[w]; az += wz[w]; }
            float* p = g_part + ((size_t)b * CHUNKS + chunk) * 3;
            p[0] = ax; p[1] = ay; p[2] = az;
            if (chunk == 0) g_maxsq[b] = 0.0f;   // zero accumulator (pre-barrier)
        }
    }
    grid_barrier(0);

    // ---- Phase B: mean from the 128 partials (identical in all blocks) ----
    {
        __shared__ float rx[4], ry[4], rz[4];
        if (t < 128) {
            const float* p = g_part + ((size_t)b * CHUNKS + t) * 3;
            float px = p[0], py = p[1], pz = p[2];
#pragma unroll
            for (int s = 16; s > 0; s >>= 1) {
                px += __shfl_down_sync(0xFFFFFFFFu, px, s);
                py += __shfl_down_sync(0xFFFFFFFFu, py, s);
                pz += __shfl_down_sync(0xFFFFFFFFu, pz, s);
            }
            if ((t & 31) == 0) { rx[t >> 5] = px; ry[t >> 5] = py; rz[t >> 5] = pz; }
        }
        __syncthreads();
        if (t == 0) {
            s_mean[0] = (rx[0] + rx[1] + rx[2] + rx[3]) / (float)NP;
            s_mean[1] = (ry[0] + ry[1] + ry[2] + ry[3]) / (float)NP;
            s_mean[2] = (rz[0] + rz[1] + rz[2] + rz[3]) / (float)NP;
        }
        __syncthreads();
    }
    const float mx = s_mean[0], my = s_mean[1], mz = s_mean[2];

    // ---- Phase C: max squared norm over this block's 512 points ----
    {
        float m = 0.f;
#pragma unroll
        for (int k = 0; k < 2; k++) {
            int i = base + t + k * 256;
            float x = cb[i]          - mx;
            float y = cb[NP + i]     - my;
            float z = cb[2 * NP + i] - mz;
            m = fmaxf(m, x * x + y * y + z * z);
        }
#pragma unroll
        for (int s = 16; s > 0; s >>= 1)
            m = fmaxf(m, __shfl_down_sync(0xFFFFFFFFu, m, s));
        if ((t & 31) == 0) wx[t >> 5] = m;
        __syncthreads();
        if (t == 0) {
#pragma unroll
            for (int w = 1; w < 8; w++) m = fmaxf(m, wx[w]);
            atomicMax((unsigned*)&g_maxsq[b], __float_as_uint(m));
        }
    }
    grid_barrier(1);

    // ---- Phase D: nc + flat ids + counts (2 points/thread via float2) ----
    if (t == 0) s_denom = 2.0f * sqrtf(g_maxsq[b]);   // EPS = 0
    __syncthreads();
    const float sc = (float)RR / s_denom;

    const float2* c2 = (const float2*)cb;
    float2* nb = (float2*)(nc_out + (size_t)b * 3 * NP);
    float* cnt = g_cnt + b * R3;
    const int j = (base >> 1) + t;            // float2 index (256 per block)

    float2 x = c2[j];
    float2 y = c2[NP / 2 + j];
    float2 z = c2[2 * (NP / 2) + j];

    x.x = fminf(fmaxf(fmaf(x.x - mx, sc, 16.0f), 0.0f), 31.0f);
    x.y = fminf(fmaxf(fmaf(x.y - mx, sc, 16.0f), 0.0f), 31.0f);
    y.x = fminf(fmaxf(fmaf(y.x - my, sc, 16.0f), 0.0f), 31.0f);
    y.y = fminf(fmaxf(fmaf(y.y - my, sc, 16.0f), 0.0f), 31.0f);
    z.x = fminf(fmaxf(fmaf(z.x - mz, sc, 16.0f), 0.0f), 31.0f);
    z.y = fminf(fmaxf(fmaf(z.y - mz, sc, 16.0f), 0.0f), 31.0f);

    __stcs(&nb[j],                x);
    __stcs(&nb[NP / 2 + j],       y);
    __stcs(&nb[2 * (NP / 2) + j], z);

    // jnp.round == round-half-to-even == rintf
    int2 fl;
    fl.x = ((int)rintf(x.x) * RR + (int)rintf(y.x)) * RR + (int)rintf(z.x);
    fl.y = ((int)rintf(x.y) * RR + (int)rintf(y.y)) * RR + (int)rintf(z.y);
    *(int2*)&g_flat[b * NP + j * 2] = fl;

    atomicAdd(&cnt[fl.x], 1.0f);
    atomicAdd(&cnt[fl.y], 1.0f);
}

// ---------------------------------------------------------------------------
// K3: feature scatter, line-coalesced atomics.
// Phase 1: coalesced STREAMING loads (lane = point, __ldcs: evict-first, so
//          the 128MB feature stream doesn't evict the freshly-memset,
//          L2-resident scratch), staged in a 128-pt x 64-ch smem tile
//          (row stride 68 floats -> conflict-free 16B groups).
// Phase 2: lanes 0-15 cover all 64 channels (256B contiguous) of point A,
//          lanes 16-31 of point B -> one red.v4 touches only 4 cache lines.
// ---------------------------------------------------------------------------
#define TPTS 128           // points per block
#define TSTR 68            // smem row stride in floats (272B = 17*16B)

__global__ __launch_bounds__(256) void scatter_kernel(const float* __restrict__ features) {
    const int blk = blockIdx.x;               // B * NP / TPTS = 4096
    const int b   = blk >> 9;                 // 512 blocks per batch
    const int n0  = (blk & 511) * TPTS;
    const int t   = threadIdx.x;              // 256

    __shared__ __align__(16) float tile[TPTS * TSTR];
    __shared__ int sflat[TPTS];

    // ---- Phase 1: load + transpose into smem ----
    {
        const int p  = t & (TPTS - 1);        // point within tile
        const int ch = (t >> 7) * 8;          // channel-quad base: 0 or 8
        const float* f = features + (size_t)b * C * NP + n0 + p;
#pragma unroll
        for (int q = 0; q < 8; q++) {
            const int c = (ch + q) * 4;
            float4 v;
            v.x = __ldcs(f + (size_t)(c + 0) * NP);
            v.y = __ldcs(f + (size_t)(c + 1) * NP);
            v.z = __ldcs(f + (size_t)(c + 2) * NP);
            v.w = __ldcs(f + (size_t)(c + 3) * NP);
            *(float4*)&tile[p * TSTR + c] = v;
        }
        if (t < TPTS) sflat[t] = g_flat[b * NP + n0 + t];
    }
    __syncthreads();

    // ---- Phase 2: coalesced-lane reds ----
    {
        const int w    = t >> 5;              // warp 0..7, 16 points each
        const int l    = t & 31;
        const int half = l >> 4;              // 0 -> point A, 1 -> point B
        const int lc   = (l & 15) * 4;        // channel offset
        float* sbase = g_scratch + (size_t)b * R3 * C;
#pragma unroll
        for (int i = 0; i < 8; i++) {
            const int p = w * 16 + 2 * i + half;
            const int flat = sflat[p];
            const float4 v = *(const float4*)&tile[p * TSTR + lc];
            float* dst = sbase + (size_t)flat * C + lc;
            asm volatile("red.global.add.v4.f32 [%0], {%1, %2, %3, %4};"
                         :: "l"(dst), "f"(v.x), "f"(v.y), "f"(v.z), "f"(v.w)
                         : "memory");
        }
    }
}

// ---------------------------------------------------------------------------
// K4: normalize by count + transpose [B][R3][C] -> [B][C][R3].
// 64-voxel tile, float4 loads, streaming float4 stores (output never re-read).
// ---------------------------------------------------------------------------
__global__ __launch_bounds__(256) void finalize_kernel(float* __restrict__ out) {
    const int blk = blockIdx.x;               // B * R3 / 64 = 4096
    const int b   = blk >> 9;                 // 512 blocks per batch
    const int v0  = (blk & 511) * 64;
    const int t   = threadIdx.x;              // 256

    __shared__ float tile[64 * 65];
    __shared__ float inv[64];

    const float4* src = (const float4*)(g_scratch + ((size_t)b * R3 + v0) * C);
#pragma unroll
    for (int it = 0; it < 4; it++) {
        const int i = t + it * 256;           // float4 index (1024 total)
        const float4 u = src[i];
        const int g = i * 4;
        const int v = g >> 6, c = g & 63;
        tile[v * 65 + c + 0] = u.x;
        tile[v * 65 + c + 1] = u.y;
        tile[v * 65 + c + 2] = u.z;
        tile[v * 65 + c + 3] = u.w;
    }
    if (t < 64) inv[t] = 1.0f / fmaxf(g_cnt[b * R3 + v0 + t], 1.0f);
    __syncthreads();

    float* dst = out + (size_t)b * C * R3 + v0;
#pragma unroll
    for (int it = 0; it < 4; it++) {
        const int i = t + it * 256;
        const int g = i * 4;
        const int c = g >> 6, v = g & 63;
        float4 r;
        r.x = tile[(v + 0) * 65 + c] * inv[v + 0];
        r.y = tile[(v + 1) * 65 + c] * inv[v + 1];
        r.z = tile[(v + 2) * 65 + c] * inv[v + 2];
        r.w = tile[(v + 3) * 65 + c] * inv[v + 3];
        __stcs((float4*)&dst[(size_t)c * R3 + v], r);
    }
}

// ---------------------------------------------------------------------------
extern "C" void kernel_launch(void* const* d_in, const int* in_sizes, int n_in,
                              void* d_out, int out_size) {
    const float* features = (const float*)d_in[0];
    const float* coords   = (const float*)d_in[1];
    if (n_in >= 2 && in_sizes[0] < in_sizes[1]) {
        features = (const float*)d_in[1];
        coords   = (const float*)d_in[0];
    }

    float* out    = (float*)d_out;
    float* nc_out = out + (size_t)B * C * R3;   // nc follows vox_feat in d_out

    void *pScratch = nullptr, *pCnt = nullptr;
    cudaGetSymbolAddress(&pScratch, g_scratch);
    cudaGetSymbolAddress(&pCnt, g_cnt);
    cudaMemsetAsync(pScratch, 0, sizeof(float) * (size_t)B * R3 * C);
    cudaMemsetAsync(pCnt,     0, sizeof(float) * (size_t)B * R3);

    fused_stats_points_kernel<<<NBLK, 256>>>(coords, nc_out);
    scatter_kernel<<<(B * NP) / TPTS, 256>>>(features);
    finalize_kernel<<<(B * R3) / 64, 256>>>(out);
}

// round 11
// speedup vs baseline: 1.6667x; 1.0520x over previous
#include <cuda_runtime.h>
#include <math.h>

#define B   8
#define C   64
#define NP  65536
#define RR  32
#define R3  32768   // 32^3

#define NBLK   1024        // fused-kernel grid (128 chunks per batch)
#define CHUNKS 128         // chunks per batch
#define CPTS   512         // points per chunk

// Scratch (device globals — no allocation allowed in kernel_launch).
// Zeroing is done inside fused_stats_points_kernel (overlapped with its
// latency-bound phases), so no memsets appear in the graph.
__device__ __align__(256) float g_scratch[(size_t)B * R3 * C]; // [B][R3][C]
__device__ __align__(256) float g_cnt[B * R3];                 // per-voxel counts
__device__ __align__(256) int   g_flat[B * NP];                // per-point voxel id
__device__ float g_maxsq[B];                      // atomicMax accumulator
__device__ float g_part[B * CHUNKS * 3];          // partial sums for mean

// Per-batch software barriers. cnt and gen live in DIFFERENT arrays and each
// slot is padded to its own 128B line: polls never contend with arrivals.
// Replay-safe: gen is monotone, cnt resets to 0 after each use.
#define BARS 32            // uints per slot = 128B
__device__ unsigned g_barcnt[2 * B * BARS];
__device__ unsigned g_bargen[2 * B * BARS];

__device__ __forceinline__ unsigned ld_acq(const unsigned* p) {
    unsigned v;
    asm volatile("ld.acquire.gpu.u32 %0, [%1];" : "=r"(v) : "l"(p));
    return v;
}

// Barrier over the 128 blocks of one batch.
__device__ __forceinline__ void batch_barrier(int slot, int b) {
    __syncthreads();
    if (threadIdx.x == 0) {
        __threadfence();
        unsigned* cnt = &g_barcnt[(slot * B + b) * BARS];
        unsigned* gen = &g_bargen[(slot * B + b) * BARS];
        const unsigned g0 = ld_acq(gen);                   // snapshot BEFORE arrive
        const unsigned old = atomicAdd(cnt, 1u);
        if (old == CHUNKS - 1) {
            atomicExch(cnt, 0u);                           // reset for next launch
            atomicAdd(gen, 1u);                            // release
        } else {
            int ns = 64;
            while (ld_acq(gen) == g0) { __nanosleep(ns); if (ns < 1024) ns <<= 1; }
        }
        __threadfence();
    }
    __syncthreads();
}

// ---------------------------------------------------------------------------
// Fused zero + stats + points kernel. Grid = 1024 blocks x 256 threads.
// __launch_bounds__(256, 7): regs <= 36 -> 7 blocks/SM co-resident
// (7 * 148 = 1036 >= 1024), required for the barriers.
// Block (b, chunk) owns points [chunk*512, (chunk+1)*512) of batch b and the
// matching batch-local slices of g_scratch (64KB) and g_cnt (256 floats).
//   Phase A: partial coord sums -> g_part; zero own scratch+cnt slices
//   ── batch barrier 0 ──
//   Phase B: re-reduce own batch's 128 partials -> mean (identical per block)
//   Phase C: local max ||c-mean||^2 -> atomicMax(g_maxsq[b]) (order-indep)
//   ── batch barrier 1 ──
//   Phase D: nc output, flat voxel ids, count atomics (2 points/thread)
// ---------------------------------------------------------------------------
__global__ __launch_bounds__(256, 7) void fused_stats_points_kernel(
        const float* __restrict__ coords, float* __restrict__ nc_out) {
    const int b     = blockIdx.x >> 7;
    const int chunk = blockIdx.x & (CHUNKS - 1);
    const int t     = threadIdx.x;            // 256
    const int base  = chunk * CPTS;
    const float* cb = coords + (size_t)b * 3 * NP;

    __shared__ float wx[8], wy[8], wz[8];
    __shared__ float s_mean[3];
    __shared__ float s_denom;

    // ---- Phase A: partial sums (512 points: 2 scalars/thread/comp) ----
    {
        const int i1 = base + t, i2 = base + t + 256;
        float sx = cb[i1] + cb[i2];
        float sy = cb[NP + i1] + cb[NP + i2];
        float sz = cb[2 * NP + i1] + cb[2 * NP + i2];
#pragma unroll
        for (int s = 16; s > 0; s >>= 1) {
            sx += __shfl_down_sync(0xFFFFFFFFu, sx, s);
            sy += __shfl_down_sync(0xFFFFFFFFu, sy, s);
            sz += __shfl_down_sync(0xFFFFFFFFu, sz, s);
        }
        if ((t & 31) == 0) { wx[t >> 5] = sx; wy[t >> 5] = sy; wz[t >> 5] = sz; }
        __syncthreads();
        if (t == 0) {
            float ax = 0.f, ay = 0.f, az = 0.f;
#pragma unroll
            for (int w = 0; w < 8; w++) { ax += wx[w]; ay += wy[w]; az += wz[w]; }
            float* p = g_part + ((size_t)b * CHUNKS + chunk) * 3;
            p[0] = ax; p[1] = ay; p[2] = az;
            if (chunk == 0) g_maxsq[b] = 0.0f;   // zero accumulator (pre-barrier)
        }
    }

    // ---- Zero own scratch slice (64KB, batch-local) + cnt slice (1KB). ----
    // Fire-and-forget STG.128s; they drain while we wait at the barrier and
    // leave the lines dirty-resident in L2 for the scatter atomics.
    {
        const float4 z4 = make_float4(0.f, 0.f, 0.f, 0.f);
        float4* zs = (float4*)(g_scratch + (size_t)blockIdx.x * (R3 * C / CHUNKS));
#pragma unroll
        for (int k = 0; k < 16; k++) zs[t + k * 256] = z4;
        g_cnt[blockIdx.x * 256 + t] = 0.0f;
    }
    batch_barrier(0, b);

    // ---- Phase B: mean from the 128 partials (identical in all blocks) ----
    {
        __shared__ float rx[4], ry[4], rz[4];
        if (t < 128) {
            const float* p = g_part + ((size_t)b * CHUNKS + t) * 3;
            float px = p[0], py = p[1], pz = p[2];
#pragma unroll
            for (int s = 16; s > 0; s >>= 1) {
                px += __shfl_down_sync(0xFFFFFFFFu, px, s);
                py += __shfl_down_sync(0xFFFFFFFFu, py, s);
                pz += __shfl_down_sync(0xFFFFFFFFu, pz, s);
            }
            if ((t & 31) == 0) { rx[t >> 5] = px; ry[t >> 5] = py; rz[t >> 5] = pz; }
        }
        __syncthreads();
        if (t == 0) {
            s_mean[0] = (rx[0] + rx[1] + rx[2] + rx[3]) / (float)NP;
            s_mean[1] = (ry[0] + ry[1] + ry[2] + ry[3]) / (float)NP;
            s_mean[2] = (rz[0] + rz[1] + rz[2] + rz[3]) / (float)NP;
        }
        __syncthreads();
    }
    const float mx = s_mean[0], my = s_mean[1], mz = s_mean[2];

    // ---- Phase C: max squared norm over this block's 512 points ----
    {
        float m = 0.f;
#pragma unroll
        for (int k = 0; k < 2; k++) {
            int i = base + t + k * 256;
            float x = cb[i]          - mx;
            float y = cb[NP + i]     - my;
            float z = cb[2 * NP + i] - mz;
            m = fmaxf(m, x * x + y * y + z * z);
        }
#pragma unroll
        for (int s = 16; s > 0; s >>= 1)
            m = fmaxf(m, __shfl_down_sync(0xFFFFFFFFu, m, s));
        if ((t & 31) == 0) wx[t >> 5] = m;
        __syncthreads();
        if (t == 0) {
#pragma unroll
            for (int w = 1; w < 8; w++) m = fmaxf(m, wx[w]);
            atomicMax((unsigned*)&g_maxsq[b], __float_as_uint(m));
        }
    }
    batch_barrier(1, b);

    // ---- Phase D: nc + flat ids + counts (2 points/thread via float2) ----
    if (t == 0) s_denom = 2.0f * sqrtf(g_maxsq[b]);   // EPS = 0
    __syncthreads();
    const float sc = (float)RR / s_denom;

    const float2* c2 = (const float2*)cb;
    float2* nb = (float2*)(nc_out + (size_t)b * 3 * NP);
    float* cnt = g_cnt + b * R3;
    const int j = (base >> 1) + t;            // float2 index (256 per block)

    float2 x = c2[j];
    float2 y = c2[NP / 2 + j];
    float2 z = c2[2 * (NP / 2) + j];

    x.x = fminf(fmaxf(fmaf(x.x - mx, sc, 16.0f), 0.0f), 31.0f);
    x.y = fminf(fmaxf(fmaf(x.y - mx, sc, 16.0f), 0.0f), 31.0f);
    y.x = fminf(fmaxf(fmaf(y.x - my, sc, 16.0f), 0.0f), 31.0f);
    y.y = fminf(fmaxf(fmaf(y.y - my, sc, 16.0f), 0.0f), 31.0f);
    z.x = fminf(fmaxf(fmaf(z.x - mz, sc, 16.0f), 0.0f), 31.0f);
    z.y = fminf(fmaxf(fmaf(z.y - mz, sc, 16.0f), 0.0f), 31.0f);

    __stcs(&nb[j],                x);
    __stcs(&nb[NP / 2 + j],       y);
    __stcs(&nb[2 * (NP / 2) + j], z);

    // jnp.round == round-half-to-even == rintf
    int2 fl;
    fl.x = ((int)rintf(x.x) * RR + (int)rintf(y.x)) * RR + (int)rintf(z.x);
    fl.y = ((int)rintf(x.y) * RR + (int)rintf(y.y)) * RR + (int)rintf(z.y);
    *(int2*)&g_flat[b * NP + j * 2] = fl;

    atomicAdd(&cnt[fl.x], 1.0f);
    atomicAdd(&cnt[fl.y], 1.0f);
}

// ---------------------------------------------------------------------------
// K3: feature scatter, line-coalesced atomics.
// Phase 1: coalesced STREAMING loads (lane = point, __ldcs: evict-first, so
//          the 128MB feature stream doesn't evict the freshly-zeroed,
//          L2-resident scratch), staged in a 128-pt x 64-ch smem tile
//          (row stride 68 floats -> conflict-free 16B groups).
// Phase 2: lanes 0-15 cover all 64 channels (256B contiguous) of point A,
//          lanes 16-31 of point B -> one red.v4 touches only 4 cache lines.
// ---------------------------------------------------------------------------
#define TPTS 128           // points per block
#define TSTR 68            // smem row stride in floats (272B = 17*16B)

__global__ __launch_bounds__(256) void scatter_kernel(const float* __restrict__ features) {
    const int blk = blockIdx.x;               // B * NP / TPTS = 4096
    const int b   = blk >> 9;                 // 512 blocks per batch
    const int n0  = (blk & 511) * TPTS;
    const int t   = threadIdx.x;              // 256

    __shared__ __align__(16) float tile[TPTS * TSTR];
    __shared__ int sflat[TPTS];

    // ---- Phase 1: load + transpose into smem ----
    {
        const int p  = t & (TPTS - 1);        // point within tile
        const int ch = (t >> 7) * 8;          // channel-quad base: 0 or 8
        const float* f = features + (size_t)b * C * NP + n0 + p;
#pragma unroll
        for (int q = 0; q < 8; q++) {
            const int c = (ch + q) * 4;
            float4 v;
            v.x = __ldcs(f + (size_t)(c + 0) * NP);
            v.y = __ldcs(f + (size_t)(c + 1) * NP);
            v.z = __ldcs(f + (size_t)(c + 2) * NP);
            v.w = __ldcs(f + (size_t)(c + 3) * NP);
            *(float4*)&tile[p * TSTR + c] = v;
        }
        if (t < TPTS) sflat[t] = g_flat[b * NP + n0 + t];
    }
    __syncthreads();

    // ---- Phase 2: coalesced-lane reds ----
    {
        const int w    = t >> 5;              // warp 0..7, 16 points each
        const int l    = t & 31;
        const int half = l >> 4;              // 0 -> point A, 1 -> point B
        const int lc   = (l & 15) * 4;        // channel offset
        float* sbase = g_scratch + (size_t)b * R3 * C;
#pragma unroll
        for (int i = 0; i < 8; i++) {
            const int p = w * 16 + 2 * i + half;
            const int flat = sflat[p];
            const float4 v = *(const float4*)&tile[p * TSTR + lc];
            float* dst = sbase + (size_t)flat * C + lc;
            asm volatile("red.global.add.v4.f32 [%0], {%1, %2, %3, %4};"
                         :: "l"(dst), "f"(v.x), "f"(v.y), "f"(v.z), "f"(v.w)
                         : "memory");
        }
    }
}

// ---------------------------------------------------------------------------
// K4: normalize by count + transpose [B][R3][C] -> [B][C][R3].
// 64-voxel tile, float4 loads, streaming float4 stores (output never re-read).
// ---------------------------------------------------------------------------
__global__ __launch_bounds__(256) void finalize_kernel(float* __restrict__ out) {
    const int blk = blockIdx.x;               // B * R3 / 64 = 4096
    const int b   = blk >> 9;                 // 512 blocks per batch
    const int v0  = (blk & 511) * 64;
    const int t   = threadIdx.x;              // 256

    __shared__ float tile[64 * 65];
    __shared__ float inv[64];

    const float4* src = (const float4*)(g_scratch + ((size_t)b * R3 + v0) * C);
#pragma unroll
    for (int it = 0; it < 4; it++) {
        const int i = t + it * 256;           // float4 index (1024 total)
        const float4 u = src[i];
        const int g = i * 4;
        const int v = g >> 6, c = g & 63;
        tile[v * 65 + c + 0] = u.x;
        tile[v * 65 + c + 1] = u.y;
        tile[v * 65 + c + 2] = u.z;
        tile[v * 65 + c + 3] = u.w;
    }
    if (t < 64) inv[t] = 1.0f / fmaxf(g_cnt[b * R3 + v0 + t], 1.0f);
    __syncthreads();

    float* dst = out + (size_t)b * C * R3 + v0;
#pragma unroll
    for (int it = 0; it < 4; it++) {
        const int i = t + it * 256;
        const int g = i * 4;
        const int c = g >> 6, v = g & 63;
        float4 r;
        r.x = tile[(v + 0) * 65 + c] * inv[v + 0];
        r.y = tile[(v + 1) * 65 + c] * inv[v + 1];
        r.z = tile[(v + 2) * 65 + c] * inv[v + 2];
        r.w = tile[(v + 3) * 65 + c] * inv[v + 3];
        __stcs((float4*)&dst[(size_t)c * R3 + v], r);
    }
}

// ---------------------------------------------------------------------------
extern "C" void kernel_launch(void* const* d_in, const int* in_sizes, int n_in,
                              void* d_out, int out_size) {
    const float* features = (const float*)d_in[0];
    const float* coords   = (const float*)d_in[1];
    if (n_in >= 2 && in_sizes[0] < in_sizes[1]) {
        features = (const float*)d_in[1];
        coords   = (const float*)d_in[0];
    }

    float* out    = (float*)d_out;
    float* nc_out = out + (size_t)B * C * R3;   // nc follows vox_feat in d_out

    fused_stats_points_kernel<<<NBLK, 256>>>(coords, nc_out);
    scatter_kernel<<<(B * NP) / TPTS, 256>>>(features);
    finalize_kernel<<<(B * R3) / 64, 256>>>(out);
}

// round 14
// speedup vs baseline: 1.6716x; 1.0030x over previous
#include <cuda_runtime.h>
#include <math.h>

#define B   8
#define C   64
#define NP  65536
#define RR  32
#define R3  32768   // 32^3

#define NBLK   1024        // fused-kernel grid (128 chunks per batch)
#define CHUNKS 128         // chunks per batch
#define CPTS   512         // points per chunk

// Scratch (device globals — no allocation allowed in kernel_launch).
// Zeroing is done at the TAIL of fused_stats_points_kernel (the kernel
// boundary orders it before scatter), so no memsets appear in the graph.
__device__ __align__(256) float g_scratch[(size_t)B * R3 * C]; // [B][R3][C]
__device__ __align__(256) float g_cnt[B * R3];                 // per-voxel counts
__device__ __align__(256) int   g_flat[B * NP];                // per-point voxel id
__device__ float g_maxsq[B];                      // atomicMax accumulator
__device__ float g_part[B * CHUNKS * 3];          // partial sums for mean

// Per-batch software barriers. cnt and gen live in DIFFERENT arrays and each
// slot is padded to its own 128B line: polls never contend with arrivals.
// Replay-safe: gen is monotone, cnt resets to 0 after each use.
#define BARS 32            // uints per slot = 128B
__device__ unsigned g_barcnt[2 * B * BARS];
__device__ unsigned g_bargen[2 * B * BARS];

__device__ __forceinline__ unsigned ld_acq(const unsigned* p) {
    unsigned v;
    asm volatile("ld.acquire.gpu.u32 %0, [%1];" : "=r"(v) : "l"(p));
    return v;
}

// Barrier over the 128 blocks of one batch.
__device__ __forceinline__ void batch_barrier(int slot, int b) {
    __syncthreads();
    if (threadIdx.x == 0) {
        __threadfence();
        unsigned* cnt = &g_barcnt[(slot * B + b) * BARS];
        unsigned* gen = &g_bargen[(slot * B + b) * BARS];
        const unsigned g0 = ld_acq(gen);                   // snapshot BEFORE arrive
        const unsigned old = atomicAdd(cnt, 1u);
        if (old == CHUNKS - 1) {
            atomicExch(cnt, 0u);                           // reset for next launch
            atomicAdd(gen, 1u);                            // release
        } else {
            int ns = 64;
            while (ld_acq(gen) == g0) { __nanosleep(ns); if (ns < 1024) ns <<= 1; }
        }
        __threadfence();
    }
    __syncthreads();
}

// ---------------------------------------------------------------------------
// Fused stats + points + scratch-zero kernel. Grid = 1024 blocks x 256 thr.
// __launch_bounds__(256, 7): regs <= 36 -> 7 blocks/SM co-resident
// (7 * 148 = 1036 >= 1024), required for the barriers.
// Block (b, chunk) owns points [chunk*512, (chunk+1)*512) of batch b and the
// matching batch-local slices of g_scratch (64KB) and g_cnt (1KB).
//   Phase A: partial coord sums -> g_part; zero own cnt slice + maxsq
//   ── batch barrier 0 ──
//   Phase B: re-reduce own batch's 128 partials -> mean (identical per block)
//   Phase C: local max ||c-mean||^2 -> atomicMax(g_maxsq[b]) (order-indep)
//   ── batch barrier 1 ──
//   Phase D: nc output, flat voxel ids, count atomics (2 points/thread)
//   Tail:    zero own 64KB scratch slice (ordered by the kernel boundary;
//            overlaps phase-D latency + retirement skew, lands dirty in L2)
// ---------------------------------------------------------------------------
__global__ __launch_bounds__(256, 7) void fused_stats_points_kernel(
        const float* __restrict__ coords, float* __restrict__ nc_out) {
    const int b     = blockIdx.x >> 7;
    const int chunk = blockIdx.x & (CHUNKS - 1);
    const int t     = threadIdx.x;            // 256
    const int base  = chunk * CPTS;
    const float* cb = coords + (size_t)b * 3 * NP;

    __shared__ float wx[8], wy[8], wz[8];
    __shared__ float s_mean[3];
    __shared__ float s_denom;

    // ---- Phase A: partial sums (512 points: 2 scalars/thread/comp) ----
    {
        const int i1 = base + t, i2 = base + t + 256;
        float sx = cb[i1] + cb[i2];
        float sy = cb[NP + i1] + cb[NP + i2];
        float sz = cb[2 * NP + i1] + cb[2 * NP + i2];
#pragma unroll
        for (int s = 16; s > 0; s >>= 1) {
            sx += __shfl_down_sync(0xFFFFFFFFu, sx, s);
            sy += __shfl_down_sync(0xFFFFFFFFu, sy, s);
            sz += __shfl_down_sync(0xFFFFFFFFu, sz, s);
        }
        if ((t & 31) == 0) { wx[t >> 5] = sx; wy[t >> 5] = sy; wz[t >> 5] = sz; }
        __syncthreads();
        if (t == 0) {
            float ax = 0.f, ay = 0.f, az = 0.f;
#pragma unroll
            for (int w = 0; w < 8; w++) { ax += wx[w]; ay += wy[w]; az += wz[w]; }
            float* p = g_part + ((size_t)b * CHUNKS + chunk) * 3;
            p[0] = ax; p[1] = ay; p[2] = az;
            if (chunk == 0) g_maxsq[b] = 0.0f;   // zero accumulator (pre-barrier)
        }
        // zero own g_cnt slice (1KB) — needed by phase-D atomics, ordered by
        // barrier 0 + 1. Small enough not to disturb the pipe.
        g_cnt[blockIdx.x * 256 + t] = 0.0f;
    }
    batch_barrier(0, b);

    // ---- Phase B: mean from the 128 partials (identical in all blocks) ----
    {
        __shared__ float rx[4], ry[4], rz[4];
        if (t < 128) {
            const float* p = g_part + ((size_t)b * CHUNKS + t) * 3;
            float px = p[0], py = p[1], pz = p[2];
#pragma unroll
            for (int s = 16; s > 0; s >>= 1) {
                px += __shfl_down_sync(0xFFFFFFFFu, px, s);
                py += __shfl_down_sync(0xFFFFFFFFu, py, s);
                pz += __shfl_down_sync(0xFFFFFFFFu, pz, s);
            }
            if ((t & 31) == 0) { rx[t >> 5] = px; ry[t >> 5] = py; rz[t >> 5] = pz; }
        }
        __syncthreads();
        if (t == 0) {
            s_mean[0] = (rx[0] + rx[1] + rx[2] + rx[3]) / (float)NP;
            s_mean[1] = (ry[0] + ry[1] + ry[2] + ry[3]) / (float)NP;
            s_mean[2] = (rz[0] + rz[1] + rz[2] + rz[3]) / (float)NP;
        }
        __syncthreads();
    }
    const float mx = s_mean[0], my = s_mean[1], mz = s_mean[2];

    // ---- Phase C: max squared norm over this block's 512 points ----
    {
        float m = 0.f;
#pragma unroll
        for (int k = 0; k < 2; k++) {
            int i = base + t + k * 256;
            float x = cb[i]          - mx;
            float y = cb[NP + i]     - my;
            float z = cb[2 * NP + i] - mz;
            m = fmaxf(m, x * x + y * y + z * z);
        }
#pragma unroll
        for (int s = 16; s > 0; s >>= 1)
            m = fmaxf(m, __shfl_down_sync(0xFFFFFFFFu, m, s));
        if ((t & 31) == 0) wx[t >> 5] = m;
        __syncthreads();
        if (t == 0) {
#pragma unroll
            for (int w = 1; w < 8; w++) m = fmaxf(m, wx[w]);
            atomicMax((unsigned*)&g_maxsq[b], __float_as_uint(m));
        }
    }
    batch_barrier(1, b);

    // ---- Phase D: nc + flat ids + counts (2 points/thread via float2) ----
    if (t == 0) s_denom = 2.0f * sqrtf(g_maxsq[b]);   // EPS = 0
    __syncthreads();
    const float sc = (float)RR / s_denom;

    const float2* c2 = (const float2*)cb;
    float2* nb = (float2*)(nc_out + (size_t)b * 3 * NP);
    float* cnt = g_cnt + b * R3;
    const int j = (base >> 1) + t;            // float2 index (256 per block)

    float2 x = c2[j];
    float2 y = c2[NP / 2 + j];
    float2 z = c2[2 * (NP / 2) + j];

    x.x = fminf(fmaxf(fmaf(x.x - mx, sc, 16.0f), 0.0f), 31.0f);
    x.y = fminf(fmaxf(fmaf(x.y - mx, sc, 16.0f), 0.0f), 31.0f);
    y.x = fminf(fmaxf(fmaf(y.x - my, sc, 16.0f), 0.0f), 31.0f);
    y.y = fminf(fmaxf(fmaf(y.y - my, sc, 16.0f), 0.0f), 31.0f);
    z.x = fminf(fmaxf(fmaf(z.x - mz, sc, 16.0f), 0.0f), 31.0f);
    z.y = fminf(fmaxf(fmaf(z.y - mz, sc, 16.0f), 0.0f), 31.0f);

    __stcs(&nb[j],                x);
    __stcs(&nb[NP / 2 + j],       y);
    __stcs(&nb[2 * (NP / 2) + j], z);

    // jnp.round == round-half-to-even == rintf
    int2 fl;
    fl.x = ((int)rintf(x.x) * RR + (int)rintf(y.x)) * RR + (int)rintf(z.x);
    fl.y = ((int)rintf(x.y) * RR + (int)rintf(y.y)) * RR + (int)rintf(z.y);
    *(int2*)&g_flat[b * NP + j * 2] = fl;

    atomicAdd(&cnt[fl.x], 1.0f);
    atomicAdd(&cnt[fl.y], 1.0f);

    // ---- Tail: zero own scratch slice (64KB, batch-local). Fire-and-forget
    // STG.128; the kernel boundary orders these before scatter's atomics, and
    // the lines land dirty-resident in L2 exactly where scatter needs them.
    {
        const float4 z4 = make_float4(0.f, 0.f, 0.f, 0.f);
        float4* zs = (float4*)(g_scratch + (size_t)blockIdx.x * (R3 * C / CHUNKS));
#pragma unroll
        for (int k = 0; k < 16; k++) zs[t + k * 256] = z4;
    }
}

// ---------------------------------------------------------------------------
// K3: feature scatter, line-coalesced atomics.
// Phase 1: coalesced STREAMING loads (lane = point, __ldcs: evict-first, so
//          the 128MB feature stream doesn't evict the freshly-zeroed,
//          L2-resident scratch), staged in a 128-pt x 64-ch smem tile
//          (row stride 68 floats -> conflict-free 16B groups).
// Phase 2: lanes 0-15 cover all 64 channels (256B contiguous) of point A,
//          lanes 16-31 of point B -> one red.v4 touches only 4 cache lines.
// ---------------------------------------------------------------------------
#define TPTS 128           // points per block
#define TSTR 68            // smem row stride in floats (272B = 17*16B)

__global__ __launch_bounds__(256) void scatter_kernel(const float* __restrict__ features) {
    const int blk = blockIdx.x;               // B * NP / TPTS = 4096
    const int b   = blk >> 9;                 // 512 blocks per batch
    const int n0  = (blk & 511) * TPTS;
    const int t   = threadIdx.x;              // 256

    __shared__ __align__(16) float tile[TPTS * TSTR];
    __shared__ int sflat[TPTS];

    // ---- Phase 1: load + transpose into smem ----
    {
        const int p  = t & (TPTS - 1);        // point within tile
        const int ch = (t >> 7) * 8;          // channel-quad base: 0 or 8
        const float* f = features + (size_t)b * C * NP + n0 + p;
#pragma unroll
        for (int q = 0; q < 8; q++) {
            const int c = (ch + q) * 4;
            float4 v;
            v.x = __ldcs(f + (size_t)(c + 0) * NP);
            v.y = __ldcs(f + (size_t)(c + 1) * NP);
            v.z = __ldcs(f + (size_t)(c + 2) * NP);
            v.w = __ldcs(f + (size_t)(c + 3) * NP);
            *(float4*)&tile[p * TSTR + c] = v;
        }
        if (t < TPTS) sflat[t] = g_flat[b * NP + n0 + t];
    }
    __syncthreads();

    // ---- Phase 2: coalesced-lane reds ----
    {
        const int w    = t >> 5;              // warp 0..7, 16 points each
        const int l    = t & 31;
        const int half = l >> 4;              // 0 -> point A, 1 -> point B
        const int lc   = (l & 15) * 4;        // channel offset
        float* sbase = g_scratch + (size_t)b * R3 * C;
#pragma unroll
        for (int i = 0; i < 8; i++) {
            const int p = w * 16 + 2 * i + half;
            const int flat = sflat[p];
            const float4 v = *(const float4*)&tile[p * TSTR + lc];
            float* dst = sbase + (size_t)flat * C + lc;
            asm volatile("red.global.add.v4.f32 [%0], {%1, %2, %3, %4};"
                         :: "l"(dst), "f"(v.x), "f"(v.y), "f"(v.z), "f"(v.w)
                         : "memory");
        }
    }
}

// ---------------------------------------------------------------------------
// K4: normalize by count + transpose [B][R3][C] -> [B][C][R3].
// 64-voxel tile, float4 loads, streaming float4 stores (output never re-read).
// ---------------------------------------------------------------------------
__global__ __launch_bounds__(256) void finalize_kernel(float* __restrict__ out) {
    const int blk = blockIdx.x;               // B * R3 / 64 = 4096
    const int b   = blk >> 9;                 // 512 blocks per batch
    const int v0  = (blk & 511) * 64;
    const int t   = threadIdx.x;              // 256

    __shared__ float tile[64 * 65];
    __shared__ float inv[64];

    const float4* src = (const float4*)(g_scratch + ((size_t)b * R3 + v0) * C);
#pragma unroll
    for (int it = 0; it < 4; it++) {
        const int i = t + it * 256;           // float4 index (1024 total)
        const float4 u = src[i];
        const int g = i * 4;
        const int v = g >> 6, c = g & 63;
        tile[v * 65 + c + 0] = u.x;
        tile[v * 65 + c + 1] = u.y;
        tile[v * 65 + c + 2] = u.z;
        tile[v * 65 + c + 3] = u.w;
    }
    if (t < 64) inv[t] = 1.0f / fmaxf(g_cnt[b * R3 + v0 + t], 1.0f);
    __syncthreads();

    float* dst = out + (size_t)b * C * R3 + v0;
#pragma unroll
    for (int it = 0; it < 4; it++) {
        const int i = t + it * 256;
        const int g = i * 4;
        const int c = g >> 6, v = g & 63;
        float4 r;
        r.x = tile[(v + 0) * 65 + c] * inv[v + 0];
        r.y = tile[(v + 1) * 65 + c] * inv[v + 1];
        r.z = tile[(v + 2) * 65 + c] * inv[v + 2];
        r.w = tile[(v + 3) * 65 + c] * inv[v + 3];
        __stcs((float4*)&dst[(size_t)c * R3 + v], r);
    }
}

// ---------------------------------------------------------------------------
extern "C" void kernel_launch(void* const* d_in, const int* in_sizes, int n_in,
                              void* d_out, int out_size) {
    const float* features = (const float*)d_in[0];
    const float* coords   = (const float*)d_in[1];
    if (n_in >= 2 && in_sizes[0] < in_sizes[1]) {
        features = (const float*)d_in[1];
        coords   = (const float*)d_in[0];
    }

    float* out    = (float*)d_out;
    float* nc_out = out + (size_t)B * C * R3;   // nc follows vox_feat in d_out

    fused_stats_points_kernel<<<NBLK, 256>>>(coords, nc_out);
    scatter_kernel<<<(B * NP) / TPTS, 256>>>(features);
    finalize_kernel<<<(B * R3) / 64, 256>>>(out);
}

// round 16
// speedup vs baseline: 1.7121x; 1.0242x over previous
#include <cuda_runtime.h>
#include <math.h>

#define B   8
#define C   64
#define NP  65536
#define RR  32
#define R3  32768   // 32^3

#define NBLK   1024        // fused-kernel grid (128 chunks per batch)
#define CHUNKS 128         // chunks per batch
#define CPTS   512         // points per chunk

// Scratch (device globals — no allocation allowed in kernel_launch).
// Zeroing is done at the TAIL of fused_stats_points_kernel; the PDL edge +
// cudaGridDependencySynchronize in scatter orders it before the atomics.
__device__ __align__(256) float g_scratch[(size_t)B * R3 * C]; // [B][R3][C]
__device__ __align__(256) float g_cnt[B * R3];                 // per-voxel counts
__device__ __align__(256) int   g_flat[B * NP];                // per-point voxel id
__device__ float g_maxsq[B];                      // atomicMax accumulator
__device__ float g_part[B * CHUNKS * 3];          // partial sums for mean

// Per-batch software barriers. cnt and gen live in DIFFERENT arrays and each
// slot is padded to its own 128B line: polls never contend with arrivals.
// Replay-safe: gen is monotone, cnt resets to 0 after each use.
#define BARS 32            // uints per slot = 128B
__device__ unsigned g_barcnt[2 * B * BARS];
__device__ unsigned g_bargen[2 * B * BARS];

__device__ __forceinline__ unsigned ld_acq(const unsigned* p) {
    unsigned v;
    asm volatile("ld.acquire.gpu.u32 %0, [%1];" : "=r"(v) : "l"(p));
    return v;
}

// Barrier over the 128 blocks of one batch.
__device__ __forceinline__ void batch_barrier(int slot, int b) {
    __syncthreads();
    if (threadIdx.x == 0) {
        __threadfence();
        unsigned* cnt = &g_barcnt[(slot * B + b) * BARS];
        unsigned* gen = &g_bargen[(slot * B + b) * BARS];
        const unsigned g0 = ld_acq(gen);                   // snapshot BEFORE arrive
        const unsigned old = atomicAdd(cnt, 1u);
        if (old == CHUNKS - 1) {
            atomicExch(cnt, 0u);                           // reset for next launch
            atomicAdd(gen, 1u);                            // release
        } else {
            int ns = 64;
            while (ld_acq(gen) == g0) { __nanosleep(ns); if (ns < 1024) ns <<= 1; }
        }
        __threadfence();
    }
    __syncthreads();
}

// ---------------------------------------------------------------------------
// Fused stats + points + scratch-zero kernel. Grid = 1024 blocks x 256 thr.
// __launch_bounds__(256, 7): regs <= 36 -> 7 blocks/SM co-resident
// (7 * 148 = 1036 >= 1024), required for the barriers.
// Coords for this block's 512 points are staged in smem in Phase A; Phases
// C and D never re-read global.
//   Phase A: load coords -> smem; partial sums -> g_part; zero cnt slice
//   ── batch barrier 0 ──
//   Phase B: re-reduce own batch's 128 partials -> mean (identical per block)
//   Phase C: local max ||c-mean||^2 (smem) -> atomicMax(g_maxsq[b])
//   ── batch barrier 1 ──
//   Phase D: nc output, flat voxel ids, count atomics (2 points/thread)
//   PDL trigger (scatter may launch; it only prefetches features until sync)
//   Tail:    zero own 64KB scratch slice — overlapped with scatter's loads
// ---------------------------------------------------------------------------
__global__ __launch_bounds__(256, 7) void fused_stats_points_kernel(
        const float* __restrict__ coords, float* __restrict__ nc_out) {
    const int b     = blockIdx.x >> 7;
    const int chunk = blockIdx.x & (CHUNKS - 1);
    const int t     = threadIdx.x;            // 256
    const int base  = chunk * CPTS;
    const float* cb = coords + (size_t)b * 3 * NP;

    __shared__ float scx[CPTS], scy[CPTS], scz[CPTS];   // 6KB coord cache
    __shared__ float wx[8], wy[8], wz[8];
    __shared__ float s_mean[3];
    __shared__ float s_denom;

    // ---- Phase A: load coords into smem + partial sums ----
    {
        const int i1 = base + t, i2 = base + t + 256;
        const float x1 = cb[i1],          x2 = cb[i2];
        const float y1 = cb[NP + i1],     y2 = cb[NP + i2];
        const float z1 = cb[2 * NP + i1], z2 = cb[2 * NP + i2];
        scx[t] = x1; scx[t + 256] = x2;
        scy[t] = y1; scy[t + 256] = y2;
        scz[t] = z1; scz[t + 256] = z2;

        float sx = x1 + x2, sy = y1 + y2, sz = z1 + z2;
#pragma unroll
        for (int s = 16; s > 0; s >>= 1) {
            sx += __shfl_down_sync(0xFFFFFFFFu, sx, s);
            sy += __shfl_down_sync(0xFFFFFFFFu, sy, s);
            sz += __shfl_down_sync(0xFFFFFFFFu, sz, s);
        }
        if ((t & 31) == 0) { wx[t >> 5] = sx; wy[t >> 5] = sy; wz[t >> 5] = sz; }
        __syncthreads();
        if (t == 0) {
            float ax = 0.f, ay = 0.f, az = 0.f;
#pragma unroll
            for (int w = 0; w < 8; w++) { ax += wx[w]; ay += wy[w]; az += wz[w]; }
            float* p = g_part + ((size_t)b * CHUNKS + chunk) * 3;
            p[0] = ax; p[1] = ay; p[2] = az;
            if (chunk == 0) g_maxsq[b] = 0.0f;   // zero accumulator (pre-barrier)
        }
        // zero own g_cnt slice (1KB) — needed by phase-D atomics, ordered by
        // barrier 0 + 1.
        g_cnt[blockIdx.x * 256 + t] = 0.0f;
    }
    batch_barrier(0, b);

    // ---- Phase B: mean from the 128 partials (identical in all blocks) ----
    {
        __shared__ float rx[4], ry[4], rz[4];
        if (t < 128) {
            const float* p = g_part + ((size_t)b * CHUNKS + t) * 3;
            float px = p[0], py = p[1], pz = p[2];
#pragma unroll
            for (int s = 16; s > 0; s >>= 1) {
                px += __shfl_down_sync(0xFFFFFFFFu, px, s);
                py += __shfl_down_sync(0xFFFFFFFFu, py, s);
                pz += __shfl_down_sync(0xFFFFFFFFu, pz, s);
            }
            if ((t & 31) == 0) { rx[t >> 5] = px; ry[t >> 5] = py; rz[t >> 5] = pz; }
        }
        __syncthreads();
        if (t == 0) {
            s_mean[0] = (rx[0] + rx[1] + rx[2] + rx[3]) / (float)NP;
            s_mean[1] = (ry[0] + ry[1] + ry[2] + ry[3]) / (float)NP;
            s_mean[2] = (rz[0] + rz[1] + rz[2] + rz[3]) / (float)NP;
        }
        __syncthreads();
    }
    const float mx = s_mean[0], my = s_mean[1], mz = s_mean[2];

    // ---- Phase C: max squared norm over this block's 512 points (smem) ----
    {
        float m = 0.f;
#pragma unroll
        for (int k = 0; k < 2; k++) {
            int i = t + k * 256;
            float x = scx[i] - mx;
            float y = scy[i] - my;
            float z = scz[i] - mz;
            m = fmaxf(m, x * x + y * y + z * z);
        }
#pragma unroll
        for (int s = 16; s > 0; s >>= 1)
            m = fmaxf(m, __shfl_down_sync(0xFFFFFFFFu, m, s));
        if ((t & 31) == 0) wx[t >> 5] = m;
        __syncthreads();
        if (t == 0) {
#pragma unroll
            for (int w = 1; w < 8; w++) m = fmaxf(m, wx[w]);
            atomicMax((unsigned*)&g_maxsq[b], __float_as_uint(m));
        }
    }
    batch_barrier(1, b);

    // ---- Phase D: nc + flat ids + counts (2 points/thread, from smem) ----
    if (t == 0) s_denom = 2.0f * sqrtf(g_maxsq[b]);   // EPS = 0
    __syncthreads();
    const float sc = (float)RR / s_denom;

    float2* nb = (float2*)(nc_out + (size_t)b * 3 * NP);
    float* cnt = g_cnt + b * R3;
    const int j = (base >> 1) + t;            // float2 index (256 per block)
    const int p0 = 2 * t;                     // local point pair

    float2 x = make_float2(scx[p0], scx[p0 + 1]);
    float2 y = make_float2(scy[p0], scy[p0 + 1]);
    float2 z = make_float2(scz[p0], scz[p0 + 1]);

    x.x = fminf(fmaxf(fmaf(x.x - mx, sc, 16.0f), 0.0f), 31.0f);
    x.y = fminf(fmaxf(fmaf(x.y - mx, sc, 16.0f), 0.0f), 31.0f);
    y.x = fminf(fmaxf(fmaf(y.x - my, sc, 16.0f), 0.0f), 31.0f);
    y.y = fminf(fmaxf(fmaf(y.y - my, sc, 16.0f), 0.0f), 31.0f);
    z.x = fminf(fmaxf(fmaf(z.x - mz, sc, 16.0f), 0.0f), 31.0f);
    z.y = fminf(fmaxf(fmaf(z.y - mz, sc, 16.0f), 0.0f), 31.0f);

    __stcs(&nb[j],                x);
    __stcs(&nb[NP / 2 + j],       y);
    __stcs(&nb[2 * (NP / 2) + j], z);

    // jnp.round == round-half-to-even == rintf
    int2 fl;
    fl.x = ((int)rintf(x.x) * RR + (int)rintf(y.x)) * RR + (int)rintf(z.x);
    fl.y = ((int)rintf(x.y) * RR + (int)rintf(y.y)) * RR + (int)rintf(z.y);
    *(int2*)&g_flat[b * NP + j * 2] = fl;

    atomicAdd(&cnt[fl.x], 1.0f);
    atomicAdd(&cnt[fl.y], 1.0f);

    // ---- PDL: let scatter launch now; it only prefetches features (input,
    // independent of this kernel) until its cudaGridDependencySynchronize.
#if __CUDA_ARCH__ >= 900
    cudaTriggerProgrammaticLaunchCompletion();
#endif

    // ---- Tail: zero own scratch slice (64KB, batch-local). Overlaps with
    // scatter's feature-load phase via the PDL edge; lines land dirty in L2.
    {
        const float4 z4 = make_float4(0.f, 0.f, 0.f, 0.f);
        float4* zs = (float4*)(g_scratch + (size_t)blockIdx.x * (R3 * C / CHUNKS));
#pragma unroll
        for (int k = 0; k < 16; k++) zs[t + k * 256] = z4;
    }
}

// ---------------------------------------------------------------------------
// K3: feature scatter, line-coalesced atomics. PDL secondary: feature loads
// (independent of the fused kernel) run before cudaGridDependencySynchronize,
// overlapping the fused kernel's zero-store tail.
// Phase 1: coalesced STREAMING loads (lane = point, __ldcs: evict-first, so
//          the 128MB feature stream doesn't evict the freshly-zeroed,
//          L2-resident scratch), staged in a 128-pt x 64-ch smem tile
//          (row stride 68 floats -> conflict-free 16B groups).
// Phase 2: lanes 0-15 cover all 64 channels (256B contiguous) of point A,
//          lanes 16-31 of point B -> one red.v4 touches only 4 cache lines.
// ---------------------------------------------------------------------------
#define TPTS 128           // points per block
#define TSTR 68            // smem row stride in floats (272B = 17*16B)

__global__ __launch_bounds__(256) void scatter_kernel(const float* __restrict__ features) {
    const int blk = blockIdx.x;               // B * NP / TPTS = 4096
    const int b   = blk >> 9;                 // 512 blocks per batch
    const int n0  = (blk & 511) * TPTS;
    const int t   = threadIdx.x;              // 256

    __shared__ __align__(16) float tile[TPTS * TSTR];
    __shared__ int sflat[TPTS];

    // ---- Phase 1: load + transpose features into smem (independent work) ----
    {
        const int p  = t & (TPTS - 1);        // point within tile
        const int ch = (t >> 7) * 8;          // channel-quad base: 0 or 8
        const float* f = features + (size_t)b * C * NP + n0 + p;
#pragma unroll
        for (int q = 0; q < 8; q++) {
            const int c = (ch + q) * 4;
            float4 v;
            v.x = __ldcs(f + (size_t)(c + 0) * NP);
            v.y = __ldcs(f + (size_t)(c + 1) * NP);
            v.z = __ldcs(f + (size_t)(c + 2) * NP);
            v.w = __ldcs(f + (size_t)(c + 3) * NP);
            *(float4*)&tile[p * TSTR + c] = v;
        }
    }

    // ---- Wait for the fused kernel (g_flat + zeroed scratch) ----
#if __CUDA_ARCH__ >= 900
    cudaGridDependencySynchronize();
#endif
    if (t < TPTS) sflat[t] = g_flat[b * NP + n0 + t];
    __syncthreads();

    // ---- Phase 2: coalesced-lane reds ----
    {
        const int w    = t >> 5;              // warp 0..7, 16 points each
        const int l    = t & 31;
        const int half = l >> 4;              // 0 -> point A, 1 -> point B
        const int lc   = (l & 15) * 4;        // channel offset
        float* sbase = g_scratch + (size_t)b * R3 * C;
#pragma unroll
        for (int i = 0; i < 8; i++) {
            const int p = w * 16 + 2 * i + half;
            const int flat = sflat[p];
            const float4 v = *(const float4*)&tile[p * TSTR + lc];
            float* dst = sbase + (size_t)flat * C + lc;
            asm volatile("red.global.add.v4.f32 [%0], {%1, %2, %3, %4};"
                         :: "l"(dst), "f"(v.x), "f"(v.y), "f"(v.z), "f"(v.w)
                         : "memory");
        }
    }
}

// ---------------------------------------------------------------------------
// K4: normalize by count + transpose [B][R3][C] -> [B][C][R3].
// 64-voxel tile, float4 loads, streaming float4 stores (output never re-read).
// ---------------------------------------------------------------------------
__global__ __launch_bounds__(256) void finalize_kernel(float* __restrict__ out) {
    const int blk = blockIdx.x;               // B * R3 / 64 = 4096
    const int b   = blk >> 9;                 // 512 blocks per batch
    const int v0  = (blk & 511) * 64;
    const int t   = threadIdx.x;              // 256

    __shared__ float tile[64 * 65];
    __shared__ float inv[64];

    const float4* src = (const float4*)(g_scratch + ((size_t)b * R3 + v0) * C);
#pragma unroll
    for (int it = 0; it < 4; it++) {
        const int i = t + it * 256;           // float4 index (1024 total)
        const float4 u = src[i];
        const int g = i * 4;
        const int v = g >> 6, c = g & 63;
        tile[v * 65 + c + 0] = u.x;
        tile[v * 65 + c + 1] = u.y;
        tile[v * 65 + c + 2] = u.z;
        tile[v * 65 + c + 3] = u.w;
    }
    if (t < 64) inv[t] = 1.0f / fmaxf(g_cnt[b * R3 + v0 + t], 1.0f);
    __syncthreads();

    float* dst = out + (size_t)b * C * R3 + v0;
#pragma unroll
    for (int it = 0; it < 4; it++) {
        const int i = t + it * 256;
        const int g = i * 4;
        const int c = g >> 6, v = g & 63;
        float4 r;
        r.x = tile[(v + 0) * 65 + c] * inv[v + 0];
        r.y = tile[(v + 1) * 65 + c] * inv[v + 1];
        r.z = tile[(v + 2) * 65 + c] * inv[v + 2];
        r.w = tile[(v + 3) * 65 + c] * inv[v + 3];
        __stcs((float4*)&dst[(size_t)c * R3 + v], r);
    }
}

// ---------------------------------------------------------------------------
extern "C" void kernel_launch(void* const* d_in, const int* in_sizes, int n_in,
                              void* d_out, int out_size) {
    const float* features = (const float*)d_in[0];
    const float* coords   = (const float*)d_in[1];
    if (n_in >= 2 && in_sizes[0] < in_sizes[1]) {
        features = (const float*)d_in[1];
        coords   = (const float*)d_in[0];
    }

    float* out    = (float*)d_out;
    float* nc_out = out + (size_t)B * C * R3;   // nc follows vox_feat in d_out

    fused_stats_points_kernel<<<NBLK, 256>>>(coords, nc_out);

    // Scatter with Programmatic Dependent Launch: starts while the fused
    // kernel drains its zero-store tail; syncs before touching its outputs.
    {
        cudaLaunchConfig_t cfg = {};
        cfg.gridDim  = dim3((B * NP) / TPTS, 1, 1);
        cfg.blockDim = dim3(256, 1, 1);
        cudaLaunchAttribute attr[1];
        attr[0].id = cudaLaunchAttributeProgrammaticStreamSerialization;
        attr[0].val.programmaticStreamSerializationAllowed = 1;
        cfg.attrs = attr;
        cfg.numAttrs = 1;
        cudaLaunchKernelEx(&cfg, scatter_kernel, features);
    }

    finalize_kernel<<<(B * R3) / 64, 256>>>(out);
}